// round 1
// baseline (speedup 1.0000x reference)
#include <cuda_runtime.h>
#include <cstdint>
#include <cstddef>

// Problem constants (fixed by the dataset)
#define D_MODEL 2048
#define SEQ     2048
#define PAST    2048
#define NHEAD   16
#define HDIM    128
#define BATCH   2
#define MROWS   (BATCH*SEQ)   // 4096

// Scratch (device globals: allocation-free per harness rules)
__device__ float g_q  [BATCH*SEQ*D_MODEL];
__device__ float g_k  [BATCH*SEQ*D_MODEL];
__device__ float g_v  [BATCH*SEQ*D_MODEL];
__device__ float g_att[BATCH*SEQ*D_MODEL];

// ---------------------------------------------------------------------------
// SGEMM: C[M,N] = A[M,K] @ W[K,N] + bias[N]   (all row-major, fp32)
// 128x128 block tile, BK=16, 256 threads, 8x8 per-thread micro-tile.
// ---------------------------------------------------------------------------
#define BM 128
#define BN 128
#define BK 16
#define TM 8
#define TN 8

__global__ __launch_bounds__(256, 2)
void sgemm_bias(const float* __restrict__ A, const float* __restrict__ W,
                const float* __restrict__ bias, float* __restrict__ C,
                int M, int N, int K)
{
    __shared__ float As[BK][BM];   // A tile stored transposed [k][m]
    __shared__ float Bs[BK][BN];   // B tile natural [k][n]

    const int tid  = threadIdx.x;
    const int tr   = tid >> 4;          // 0..15  (row group)
    const int tc   = tid & 15;          // 0..15  (col group)
    const int row0 = blockIdx.y * BM;
    const int col0 = blockIdx.x * BN;

    const int aRow = tid >> 2;          // 0..63
    const int aCol = (tid & 3) << 2;    // 0,4,8,12
    const int bRow = tid >> 5;          // 0..7
    const int bCol = (tid & 31) << 2;   // 0..124

    const float* Ag = A + (size_t)row0 * K;
    const float* Wg = W + col0;

    float acc[TM][TN];
    #pragma unroll
    for (int i = 0; i < TM; i++)
        #pragma unroll
        for (int j = 0; j < TN; j++) acc[i][j] = 0.f;

    for (int k0 = 0; k0 < K; k0 += BK) {
        #pragma unroll
        for (int s = 0; s < 2; s++) {
            int r = aRow + s*64;
            float4 v = *(const float4*)(Ag + (size_t)r*K + k0 + aCol);
            As[aCol+0][r] = v.x;
            As[aCol+1][r] = v.y;
            As[aCol+2][r] = v.z;
            As[aCol+3][r] = v.w;
        }
        #pragma unroll
        for (int s = 0; s < 2; s++) {
            int r = bRow + s*8;
            *(float4*)(&Bs[r][bCol]) = *(const float4*)(Wg + (size_t)(k0+r)*N + bCol);
        }
        __syncthreads();

        #pragma unroll
        for (int k = 0; k < BK; k++) {
            float af[TM], bf[TN];
            *(float4*)(af)   = *(const float4*)(&As[k][tr*TM]);
            *(float4*)(af+4) = *(const float4*)(&As[k][tr*TM+4]);
            *(float4*)(bf)   = *(const float4*)(&Bs[k][tc*TN]);
            *(float4*)(bf+4) = *(const float4*)(&Bs[k][tc*TN+4]);
            #pragma unroll
            for (int i = 0; i < TM; i++)
                #pragma unroll
                for (int j = 0; j < TN; j++)
                    acc[i][j] = fmaf(af[i], bf[j], acc[i][j]);
        }
        __syncthreads();
    }

    #pragma unroll
    for (int i = 0; i < TM; i++) {
        int r = row0 + tr*TM + i;
        #pragma unroll
        for (int j = 0; j < TN; j += 4) {
            int c = col0 + tc*TN + j;
            float4 ov;
            ov.x = acc[i][j+0] + bias[c+0];
            ov.y = acc[i][j+1] + bias[c+1];
            ov.z = acc[i][j+2] + bias[c+2];
            ov.w = acc[i][j+3] + bias[c+3];
            *(float4*)(C + (size_t)r*N + c) = ov;
        }
    }
}

// ---------------------------------------------------------------------------
// Flash attention (fp32, online softmax, no mask).
// Block: 64 queries x one (b,h). KV loop in 64-key tiles over [cache | new].
// Thread layout 16x16: scores micro-tile 4x4, O micro-tile 4(rows)x8(dims).
// ---------------------------------------------------------------------------
#define ATTN_SMEM (28672 * 4)   // Qs 128x64 + Ks 128x64 + Vs 64x128 + Ps 64x64

__global__ __launch_bounds__(256, 2)
void attn_kernel(const float* __restrict__ cache_k, const float* __restrict__ cache_v)
{
    extern __shared__ float sm[];
    float* Qs = sm;            // [128][64]  (transposed: [d][i])
    float* Ks = sm + 8192;     // [128][64]  (transposed: [d][j])
    float* Vs = sm + 16384;    // [64][128]  (natural:    [j][d])
    float* Ps = sm + 24576;    // [64][64]   (natural:    [i][j])

    const int tid = threadIdx.x;
    const int ty  = tid >> 4;   // 0..15: owns query rows ty*4..ty*4+3
    const int tx  = tid & 15;   // 0..15: score cols tx*4.., O dims tx*8..
    const int b   = blockIdx.z;
    const int h   = blockIdx.y;
    const int q0  = blockIdx.x * 64;

    const float NEG_INF = -__int_as_float(0x7f800000);

    // Load Q tile transposed into smem
    const float* qptr = g_q + ((size_t)(b*SEQ + q0))*D_MODEL + h*HDIM;
    for (int t = tid; t < 64*32; t += 256) {
        int i = t >> 5;
        int d = (t & 31) << 2;
        float4 v = *(const float4*)(qptr + (size_t)i*D_MODEL + d);
        Qs[(d+0)*64 + i] = v.x;
        Qs[(d+1)*64 + i] = v.y;
        Qs[(d+2)*64 + i] = v.z;
        Qs[(d+3)*64 + i] = v.w;
    }

    float m[4], l[4], o[4][8];
    #pragma unroll
    for (int r = 0; r < 4; r++) {
        m[r] = NEG_INF;
        l[r] = 0.f;
        #pragma unroll
        for (int c = 0; c < 8; c++) o[r][c] = 0.f;
    }
    __syncthreads();

    const float sc = 0.08838834764831845f;  // 1/sqrt(128)

    for (int kv0 = 0; kv0 < PAST + SEQ; kv0 += 64) {
        const float *kb, *vb;
        if (kv0 < PAST) {
            size_t off = ((size_t)(b*PAST + kv0))*D_MODEL + h*HDIM;
            kb = cache_k + off;
            vb = cache_v + off;
        } else {
            size_t off = ((size_t)(b*SEQ + (kv0 - PAST)))*D_MODEL + h*HDIM;
            kb = g_k + off;
            vb = g_v + off;
        }

        // Load K (transposed) and V (natural) tiles
        for (int t = tid; t < 64*32; t += 256) {
            int j = t >> 5;
            int d = (t & 31) << 2;
            float4 kvv = *(const float4*)(kb + (size_t)j*D_MODEL + d);
            Ks[(d+0)*64 + j] = kvv.x;
            Ks[(d+1)*64 + j] = kvv.y;
            Ks[(d+2)*64 + j] = kvv.z;
            Ks[(d+3)*64 + j] = kvv.w;
            *(float4*)(Vs + j*HDIM + d) = *(const float4*)(vb + (size_t)j*D_MODEL + d);
        }
        __syncthreads();

        // Scores: s[r][c] = Q[ty*4+r] . K[tx*4+c]
        float s[4][4];
        #pragma unroll
        for (int r = 0; r < 4; r++)
            #pragma unroll
            for (int c = 0; c < 4; c++) s[r][c] = 0.f;

        #pragma unroll 4
        for (int d = 0; d < HDIM; d++) {
            float qa[4], ka[4];
            *(float4*)qa = *(const float4*)(Qs + d*64 + ty*4);
            *(float4*)ka = *(const float4*)(Ks + d*64 + tx*4);
            #pragma unroll
            for (int r = 0; r < 4; r++)
                #pragma unroll
                for (int c = 0; c < 4; c++)
                    s[r][c] = fmaf(qa[r], ka[c], s[r][c]);
        }

        // Online softmax across the 16 tx lanes (width-16 shuffles)
        float alpha[4];
        #pragma unroll
        for (int r = 0; r < 4; r++) {
            float mx = NEG_INF;
            #pragma unroll
            for (int c = 0; c < 4; c++) {
                s[r][c] *= sc;
                mx = fmaxf(mx, s[r][c]);
            }
            #pragma unroll
            for (int off = 8; off > 0; off >>= 1)
                mx = fmaxf(mx, __shfl_xor_sync(0xffffffffu, mx, off, 16));
            float mn = fmaxf(m[r], mx);
            float sum = 0.f;
            #pragma unroll
            for (int c = 0; c < 4; c++) {
                float p = __expf(s[r][c] - mn);
                s[r][c] = p;
                sum += p;
            }
            #pragma unroll
            for (int off = 8; off > 0; off >>= 1)
                sum += __shfl_xor_sync(0xffffffffu, sum, off, 16);
            alpha[r] = __expf(m[r] - mn);
            l[r] = l[r]*alpha[r] + sum;
            m[r] = mn;
            // store P row-major [i][j]
            *(float4*)(Ps + (ty*4+r)*64 + tx*4) = *(float4*)(s[r]);
        }
        __syncthreads();

        // O = O*alpha + P @ V
        #pragma unroll
        for (int r = 0; r < 4; r++)
            #pragma unroll
            for (int c = 0; c < 8; c++)
                o[r][c] *= alpha[r];

        #pragma unroll 2
        for (int j = 0; j < 64; j++) {
            float vv[8];
            *(float4*)(vv)   = *(const float4*)(Vs + j*HDIM + tx*8);
            *(float4*)(vv+4) = *(const float4*)(Vs + j*HDIM + tx*8 + 4);
            #pragma unroll
            for (int r = 0; r < 4; r++) {
                float p = Ps[(ty*4+r)*64 + j];
                #pragma unroll
                for (int c = 0; c < 8; c++)
                    o[r][c] = fmaf(p, vv[c], o[r][c]);
            }
        }
        __syncthreads();
    }

    // Normalize and write out (heads re-merged into D slices)
    float* optr = g_att + ((size_t)(b*SEQ + q0))*D_MODEL + h*HDIM;
    #pragma unroll
    for (int r = 0; r < 4; r++) {
        float inv = 1.f / l[r];
        float4 o0, o1;
        o0.x = o[r][0]*inv; o0.y = o[r][1]*inv; o0.z = o[r][2]*inv; o0.w = o[r][3]*inv;
        o1.x = o[r][4]*inv; o1.y = o[r][5]*inv; o1.z = o[r][6]*inv; o1.w = o[r][7]*inv;
        float* dst = optr + (size_t)(ty*4+r)*D_MODEL + tx*8;
        *(float4*)(dst)     = o0;
        *(float4*)(dst + 4) = o1;
    }
}

// ---------------------------------------------------------------------------
// Launch
// ---------------------------------------------------------------------------
extern "C" void kernel_launch(void* const* d_in, const int* in_sizes, int n_in,
                              void* d_out, int out_size)
{
    (void)in_sizes; (void)n_in; (void)out_size;
    const float* x  = (const float*)d_in[0];
    const float* ck = (const float*)d_in[1];
    const float* cv = (const float*)d_in[2];
    const float* wq = (const float*)d_in[3];
    const float* bq = (const float*)d_in[4];
    const float* wk = (const float*)d_in[5];
    const float* bk = (const float*)d_in[6];
    const float* wv = (const float*)d_in[7];
    const float* bv = (const float*)d_in[8];
    const float* wo = (const float*)d_in[9];
    const float* bo = (const float*)d_in[10];
    float* out = (float*)d_out;

    float *pq, *pk, *pv, *pa;
    cudaGetSymbolAddress((void**)&pq, g_q);
    cudaGetSymbolAddress((void**)&pk, g_k);
    cudaGetSymbolAddress((void**)&pv, g_v);
    cudaGetSymbolAddress((void**)&pa, g_att);

    cudaFuncSetAttribute(attn_kernel, cudaFuncAttributeMaxDynamicSharedMemorySize, ATTN_SMEM);

    dim3 gg(D_MODEL/BN, MROWS/BM);
    sgemm_bias<<<gg, 256>>>(x, wq, bq, pq, MROWS, D_MODEL, D_MODEL);
    sgemm_bias<<<gg, 256>>>(x, wk, bk, pk, MROWS, D_MODEL, D_MODEL);
    sgemm_bias<<<gg, 256>>>(x, wv, bv, pv, MROWS, D_MODEL, D_MODEL);

    dim3 ag(SEQ/64, NHEAD, BATCH);
    attn_kernel<<<ag, 256, ATTN_SMEM>>>(ck, cv);

    sgemm_bias<<<gg, 256>>>(pa, wo, bo, out, MROWS, D_MODEL, D_MODEL);
}

// round 3
// speedup vs baseline: 1.3331x; 1.3331x over previous
#include <cuda_runtime.h>
#include <cstdint>
#include <cstddef>

// Problem constants
#define D_MODEL 2048
#define SEQ     2048
#define PAST    2048
#define NHEAD   16
#define HDIM    128
#define BATCH   2
#define MROWS   (BATCH*SEQ)   // 4096

// Scratch (device globals — allocation-free per harness rules)
__device__ float g_q  [MROWS*D_MODEL];
__device__ float g_k  [MROWS*D_MODEL];
__device__ float g_v  [MROWS*D_MODEL];
__device__ float g_att[MROWS*D_MODEL];
__device__ float g_x32[MROWS*D_MODEL];          // tf32-rounded x
__device__ float g_wt [4*(size_t)D_MODEL*D_MODEL]; // transposed+tf32-rounded weights

// ---------------------------------------------------------------------------
// helpers
// ---------------------------------------------------------------------------
__device__ __forceinline__ float to_tf32(float f) {
    uint32_t o;
    asm("cvt.rna.tf32.f32 %0, %1;" : "=r"(o) : "f"(f));
    return __uint_as_float(o);
}
__device__ __forceinline__ uint32_t smem_u32(const void* p) {
    uint32_t a;
    asm("{ .reg .u64 t; cvta.to.shared.u64 t, %1; cvt.u32.u64 %0, t; }" : "=r"(a) : "l"(p));
    return a;
}
__device__ __forceinline__ void cp_async16(uint32_t sdst, const void* gsrc) {
    asm volatile("cp.async.cg.shared.global [%0], [%1], 16;" :: "r"(sdst), "l"(gsrc));
}
__device__ __forceinline__ void cp_commit() {
    asm volatile("cp.async.commit_group;");
}
template<int N>
__device__ __forceinline__ void cp_wait() {
    asm volatile("cp.async.wait_group %0;" :: "n"(N));
}
__device__ __forceinline__ void mma_tf32(float& c0, float& c1, float& c2, float& c3,
                                         uint32_t a0, uint32_t a1, uint32_t a2, uint32_t a3,
                                         uint32_t b0, uint32_t b1) {
    asm volatile("mma.sync.aligned.m16n8k8.row.col.f32.tf32.tf32.f32 "
                 "{%0,%1,%2,%3}, {%4,%5,%6,%7}, {%8,%9}, {%0,%1,%2,%3};"
                 : "+f"(c0), "+f"(c1), "+f"(c2), "+f"(c3)
                 : "r"(a0), "r"(a1), "r"(a2), "r"(a3), "r"(b0), "r"(b1));
}

// ---------------------------------------------------------------------------
// Tensor-core GEMM (mma.sync tf32):  C[M,2048] = A[M,2048] @ Bt^T + bias
//   A  : row-major [M][K]      (K contiguous)  -- tf32-rounded fp32
//   Bt : row-major [N][K]      (K contiguous)  -- transposed weight, tf32-rounded
// CTA tile 128x256, BK=32, 8 warps (2x4), warp tile 64x64.
// ---------------------------------------------------------------------------
#define GBM 128
#define GBN 256
#define GBK 32
#define SROW 36                                // padded row stride (floats)
#define AS_FLOATS (GBM*SROW)                   // 4608
#define BS_FLOATS (GBN*SROW)                   // 9216
#define STG_FLOATS (AS_FLOATS + BS_FLOATS)     // 13824
#define GEMM_DSMEM (2*STG_FLOATS*4)            // 110592 bytes
#define NCHUNK (D_MODEL/GBK)                   // 64

__global__ __launch_bounds__(256, 1)
void gemm_tc(const float* __restrict__ A, const float* __restrict__ Bt,
             const float* __restrict__ bias, float* __restrict__ C)
{
    extern __shared__ float smem[];
    // stage s: As at smem + s*STG_FLOATS, Bs at + AS_FLOATS
    const uint32_t smem_base = smem_u32(smem);

    const int tid  = threadIdx.x;
    const int wid  = tid >> 5;
    const int lane = tid & 31;
    const int r    = lane >> 2;     // 0..7
    const int cc   = lane & 3;      // 0..3

    const int m0 = blockIdx.y * GBM;
    const int n0 = blockIdx.x * GBN;
    const int wm = (wid >> 2) * 64;   // 0 or 64
    const int wn = (wid & 3) * 64;    // 0,64,128,192

    // gmem load mapping: 16B segments. A: 1024 segs (4/thread), B: 2048 (8/thread)
    const int a_row0 = tid >> 3;           // rows tid/8, +32 per i
    const int a_seg  = tid & 7;            // 0..7 (16B seg within 32-float row)
    const float* Ag = A  + (size_t)(m0 + a_row0) * D_MODEL + a_seg * 4;
    const float* Bg = Bt + (size_t)(n0 + a_row0) * D_MODEL + a_seg * 4;

    float c[4][8][4];
    #pragma unroll
    for (int mi = 0; mi < 4; mi++)
        #pragma unroll
        for (int ni = 0; ni < 8; ni++)
            #pragma unroll
            for (int j = 0; j < 4; j++) c[mi][ni][j] = 0.f;

    // Issue one chunk's cp.asyncs into stage st
    auto load_chunk = [&](int chunk, int st) {
        uint32_t as = smem_base + (st*STG_FLOATS) * 4;
        uint32_t bs = as + AS_FLOATS * 4;
        const float* ag = Ag + chunk * GBK;
        const float* bg = Bg + chunk * GBK;
        #pragma unroll
        for (int i = 0; i < 4; i++) {
            int row = a_row0 + i * 32;
            cp_async16(as + (row*SROW + a_seg*4) * 4, ag + (size_t)i*32*D_MODEL);
        }
        #pragma unroll
        for (int i = 0; i < 8; i++) {
            int row = a_row0 + i * 32;
            cp_async16(bs + (row*SROW + a_seg*4) * 4, bg + (size_t)i*32*D_MODEL);
        }
        cp_commit();
    };

    load_chunk(0, 0);
    load_chunk(1, 1);

    for (int ch = 0; ch < NCHUNK; ch++) {
        if (ch == NCHUNK-1) cp_wait<0>(); else cp_wait<1>();
        __syncthreads();

        const float* As = smem + (ch & 1) * STG_FLOATS;
        const float* Bs = As + AS_FLOATS;
        const float* pA = As + (wm + r) * SROW + cc;
        const float* pB = Bs + (wn + r) * SROW + cc;

        #pragma unroll
        for (int ks = 0; ks < 4; ks++) {
            uint32_t a[4][4];
            #pragma unroll
            for (int mi = 0; mi < 4; mi++) {
                const float* p = pA + mi*16*SROW + ks*8;
                a[mi][0] = __float_as_uint(p[0]);
                a[mi][1] = __float_as_uint(p[8*SROW]);
                a[mi][2] = __float_as_uint(p[4]);
                a[mi][3] = __float_as_uint(p[8*SROW + 4]);
            }
            uint32_t b[8][2];
            #pragma unroll
            for (int ni = 0; ni < 8; ni++) {
                const float* p = pB + ni*8*SROW + ks*8;
                b[ni][0] = __float_as_uint(p[0]);
                b[ni][1] = __float_as_uint(p[4]);
            }
            #pragma unroll
            for (int mi = 0; mi < 4; mi++)
                #pragma unroll
                for (int ni = 0; ni < 8; ni++)
                    mma_tf32(c[mi][ni][0], c[mi][ni][1], c[mi][ni][2], c[mi][ni][3],
                             a[mi][0], a[mi][1], a[mi][2], a[mi][3],
                             b[ni][0], b[ni][1]);
        }
        __syncthreads();
        if (ch + 2 < NCHUNK) load_chunk(ch + 2, ch & 1);
    }

    // Epilogue: c0,c1 at (row, col..col+1); c2,c3 at (row+8, ...)
    #pragma unroll
    for (int mi = 0; mi < 4; mi++) {
        int row = m0 + wm + mi*16 + r;
        #pragma unroll
        for (int ni = 0; ni < 8; ni++) {
            int col = n0 + wn + ni*8 + cc*2;
            float2 bv = *(const float2*)(bias + col);
            float2 o0, o1;
            o0.x = c[mi][ni][0] + bv.x;  o0.y = c[mi][ni][1] + bv.y;
            o1.x = c[mi][ni][2] + bv.x;  o1.y = c[mi][ni][3] + bv.y;
            *(float2*)(C + (size_t)row * D_MODEL + col)       = o0;
            *(float2*)(C + (size_t)(row+8) * D_MODEL + col)   = o1;
        }
    }
}

// ---------------------------------------------------------------------------
// Prep kernels: tf32 rounding + weight transpose (with tf32 rounding)
// ---------------------------------------------------------------------------
__global__ void cvt_tf32_kernel(const float4* __restrict__ src, float4* __restrict__ dst, int n4)
{
    int i = blockIdx.x * blockDim.x + threadIdx.x;
    if (i < n4) {
        float4 v = src[i];
        v.x = to_tf32(v.x); v.y = to_tf32(v.y); v.z = to_tf32(v.z); v.w = to_tf32(v.w);
        dst[i] = v;
    }
}

__global__ void transpose_cvt(const float* __restrict__ src, float* __restrict__ dst)
{
    __shared__ float t[32][33];
    int bx = blockIdx.x * 32, by = blockIdx.y * 32;
    int x = bx + threadIdx.x;
    #pragma unroll
    for (int i = 0; i < 32; i += 8)
        t[threadIdx.y + i][threadIdx.x] = src[(size_t)(by + threadIdx.y + i) * D_MODEL + x];
    __syncthreads();
    x = by + threadIdx.x;
    #pragma unroll
    for (int i = 0; i < 32; i += 8)
        dst[(size_t)(bx + threadIdx.y + i) * D_MODEL + x] = to_tf32(t[threadIdx.x][threadIdx.y + i]);
}

// ---------------------------------------------------------------------------
// Flash attention (fp32, online softmax) — tf32-rounds its output
// ---------------------------------------------------------------------------
#define ATTN_SMEM (28672 * 4)

__global__ __launch_bounds__(256, 2)
void attn_kernel(const float* __restrict__ cache_k, const float* __restrict__ cache_v)
{
    extern __shared__ float sm[];
    float* Qs = sm;            // [128][64]
    float* Ks = sm + 8192;     // [128][64]
    float* Vs = sm + 16384;    // [64][128]
    float* Ps = sm + 24576;    // [64][64]

    const int tid = threadIdx.x;
    const int ty  = tid >> 4;
    const int tx  = tid & 15;
    const int b   = blockIdx.z;
    const int h   = blockIdx.y;
    const int q0  = blockIdx.x * 64;

    const float NEG_INF = -__int_as_float(0x7f800000);

    const float* qptr = g_q + ((size_t)(b*SEQ + q0))*D_MODEL + h*HDIM;
    for (int t = tid; t < 64*32; t += 256) {
        int i = t >> 5;
        int d = (t & 31) << 2;
        float4 v = *(const float4*)(qptr + (size_t)i*D_MODEL + d);
        Qs[(d+0)*64 + i] = v.x;
        Qs[(d+1)*64 + i] = v.y;
        Qs[(d+2)*64 + i] = v.z;
        Qs[(d+3)*64 + i] = v.w;
    }

    float m[4], l[4], o[4][8];
    #pragma unroll
    for (int r = 0; r < 4; r++) {
        m[r] = NEG_INF; l[r] = 0.f;
        #pragma unroll
        for (int c = 0; c < 8; c++) o[r][c] = 0.f;
    }
    __syncthreads();

    const float sc = 0.08838834764831845f;

    for (int kv0 = 0; kv0 < PAST + SEQ; kv0 += 64) {
        const float *kb, *vb;
        if (kv0 < PAST) {
            size_t off = ((size_t)(b*PAST + kv0))*D_MODEL + h*HDIM;
            kb = cache_k + off; vb = cache_v + off;
        } else {
            size_t off = ((size_t)(b*SEQ + (kv0 - PAST)))*D_MODEL + h*HDIM;
            kb = g_k + off; vb = g_v + off;
        }

        for (int t = tid; t < 64*32; t += 256) {
            int j = t >> 5;
            int d = (t & 31) << 2;
            float4 kvv = *(const float4*)(kb + (size_t)j*D_MODEL + d);
            Ks[(d+0)*64 + j] = kvv.x;
            Ks[(d+1)*64 + j] = kvv.y;
            Ks[(d+2)*64 + j] = kvv.z;
            Ks[(d+3)*64 + j] = kvv.w;
            *(float4*)(Vs + j*HDIM + d) = *(const float4*)(vb + (size_t)j*D_MODEL + d);
        }
        __syncthreads();

        float s[4][4];
        #pragma unroll
        for (int r = 0; r < 4; r++)
            #pragma unroll
            for (int c = 0; c < 4; c++) s[r][c] = 0.f;

        #pragma unroll 4
        for (int d = 0; d < HDIM; d++) {
            float qa[4], ka[4];
            *(float4*)qa = *(const float4*)(Qs + d*64 + ty*4);
            *(float4*)ka = *(const float4*)(Ks + d*64 + tx*4);
            #pragma unroll
            for (int r = 0; r < 4; r++)
                #pragma unroll
                for (int c = 0; c < 4; c++)
                    s[r][c] = fmaf(qa[r], ka[c], s[r][c]);
        }

        float alpha[4];
        #pragma unroll
        for (int r = 0; r < 4; r++) {
            float mx = NEG_INF;
            #pragma unroll
            for (int c = 0; c < 4; c++) {
                s[r][c] *= sc;
                mx = fmaxf(mx, s[r][c]);
            }
            #pragma unroll
            for (int off = 8; off > 0; off >>= 1)
                mx = fmaxf(mx, __shfl_xor_sync(0xffffffffu, mx, off, 16));
            float mn = fmaxf(m[r], mx);
            float sum = 0.f;
            #pragma unroll
            for (int c = 0; c < 4; c++) {
                float p = __expf(s[r][c] - mn);
                s[r][c] = p;
                sum += p;
            }
            #pragma unroll
            for (int off = 8; off > 0; off >>= 1)
                sum += __shfl_xor_sync(0xffffffffu, sum, off, 16);
            alpha[r] = __expf(m[r] - mn);
            l[r] = l[r]*alpha[r] + sum;
            m[r] = mn;
            *(float4*)(Ps + (ty*4+r)*64 + tx*4) = *(float4*)(s[r]);
        }
        __syncthreads();

        #pragma unroll
        for (int r = 0; r < 4; r++)
            #pragma unroll
            for (int c = 0; c < 8; c++)
                o[r][c] *= alpha[r];

        #pragma unroll 2
        for (int j = 0; j < 64; j++) {
            float vv[8];
            *(float4*)(vv)   = *(const float4*)(Vs + j*HDIM + tx*8);
            *(float4*)(vv+4) = *(const float4*)(Vs + j*HDIM + tx*8 + 4);
            #pragma unroll
            for (int r = 0; r < 4; r++) {
                float p = Ps[(ty*4+r)*64 + j];
                #pragma unroll
                for (int c = 0; c < 8; c++)
                    o[r][c] = fmaf(p, vv[c], o[r][c]);
            }
        }
        __syncthreads();
    }

    // tf32-rounded output (feeds the tensor-core out-projection as A operand)
    float* optr = g_att + ((size_t)(b*SEQ + q0))*D_MODEL + h*HDIM;
    #pragma unroll
    for (int r = 0; r < 4; r++) {
        float inv = 1.f / l[r];
        float4 o0, o1;
        o0.x = to_tf32(o[r][0]*inv); o0.y = to_tf32(o[r][1]*inv);
        o0.z = to_tf32(o[r][2]*inv); o0.w = to_tf32(o[r][3]*inv);
        o1.x = to_tf32(o[r][4]*inv); o1.y = to_tf32(o[r][5]*inv);
        o1.z = to_tf32(o[r][6]*inv); o1.w = to_tf32(o[r][7]*inv);
        float* dstp = optr + (size_t)(ty*4+r)*D_MODEL + tx*8;
        *(float4*)(dstp)     = o0;
        *(float4*)(dstp + 4) = o1;
    }
}

// ---------------------------------------------------------------------------
// Launch
// ---------------------------------------------------------------------------
extern "C" void kernel_launch(void* const* d_in, const int* in_sizes, int n_in,
                              void* d_out, int out_size)
{
    (void)in_sizes; (void)n_in; (void)out_size;
    const float* x  = (const float*)d_in[0];
    const float* ck = (const float*)d_in[1];
    const float* cv = (const float*)d_in[2];
    const float* wq = (const float*)d_in[3];
    const float* bq = (const float*)d_in[4];
    const float* wk = (const float*)d_in[5];
    const float* bk = (const float*)d_in[6];
    const float* wv = (const float*)d_in[7];
    const float* bv = (const float*)d_in[8];
    const float* wo = (const float*)d_in[9];
    const float* bo = (const float*)d_in[10];
    float* out = (float*)d_out;

    float *pq, *pk, *pv, *pa, *px, *pw;
    cudaGetSymbolAddress((void**)&pq, g_q);
    cudaGetSymbolAddress((void**)&pk, g_k);
    cudaGetSymbolAddress((void**)&pv, g_v);
    cudaGetSymbolAddress((void**)&pa, g_att);
    cudaGetSymbolAddress((void**)&px, g_x32);
    cudaGetSymbolAddress((void**)&pw, g_wt);

    float* wt_q = pw + 0*(size_t)D_MODEL*D_MODEL;
    float* wt_k = pw + 1*(size_t)D_MODEL*D_MODEL;
    float* wt_v = pw + 2*(size_t)D_MODEL*D_MODEL;
    float* wt_o = pw + 3*(size_t)D_MODEL*D_MODEL;

    cudaFuncSetAttribute(gemm_tc,     cudaFuncAttributeMaxDynamicSharedMemorySize, GEMM_DSMEM);
    cudaFuncSetAttribute(attn_kernel, cudaFuncAttributeMaxDynamicSharedMemorySize, ATTN_SMEM);

    // Prep: tf32-round x; transpose + tf32-round weights
    int n4 = MROWS*D_MODEL/4;
    cvt_tf32_kernel<<<(n4 + 255)/256, 256>>>((const float4*)x, (float4*)px, n4);
    dim3 tg(D_MODEL/32, D_MODEL/32), tb(32, 8);
    transpose_cvt<<<tg, tb>>>(wq, wt_q);
    transpose_cvt<<<tg, tb>>>(wk, wt_k);
    transpose_cvt<<<tg, tb>>>(wv, wt_v);
    transpose_cvt<<<tg, tb>>>(wo, wt_o);

    // Projections on tensor cores (mma.sync tf32)
    dim3 gg(D_MODEL/GBN, MROWS/GBM);   // (8, 32)
    gemm_tc<<<gg, 256, GEMM_DSMEM>>>(px, wt_q, bq, pq);
    gemm_tc<<<gg, 256, GEMM_DSMEM>>>(px, wt_k, bk, pk);
    gemm_tc<<<gg, 256, GEMM_DSMEM>>>(px, wt_v, bv, pv);

    // Attention (fp32)
    dim3 ag(SEQ/64, NHEAD, BATCH);
    attn_kernel<<<ag, 256, ATTN_SMEM>>>(ck, cv);

    // Output projection on tensor cores
    gemm_tc<<<gg, 256, GEMM_DSMEM>>>(pa, wt_o, bo, out);
}

// round 4
// speedup vs baseline: 4.0599x; 3.0454x over previous
#include <cuda_runtime.h>
#include <cstdint>
#include <cstddef>

// Problem constants
#define D_MODEL 2048
#define SEQ     2048
#define PAST    2048
#define NHEAD   16
#define HDIM    128
#define BATCH   2
#define MROWS   (BATCH*SEQ)   // 4096

// Scratch (device globals — allocation-free per harness rules)
__device__ float g_q  [MROWS*D_MODEL];
__device__ float g_k  [MROWS*D_MODEL];
__device__ float g_v  [MROWS*D_MODEL];
__device__ float g_att[MROWS*D_MODEL];
__device__ float g_x32[MROWS*D_MODEL];             // tf32-rounded x
__device__ float g_ck [BATCH*PAST*D_MODEL];        // tf32-rounded cache_k
__device__ float g_cv [BATCH*PAST*D_MODEL];        // tf32-rounded cache_v
__device__ float g_wt [4*(size_t)D_MODEL*D_MODEL]; // transposed+tf32-rounded weights

// ---------------------------------------------------------------------------
// helpers
// ---------------------------------------------------------------------------
__device__ __forceinline__ float to_tf32(float f) {
    uint32_t o;
    asm("cvt.rna.tf32.f32 %0, %1;" : "=r"(o) : "f"(f));
    return __uint_as_float(o);
}
__device__ __forceinline__ uint32_t smem_u32(const void* p) {
    uint32_t a;
    asm("{ .reg .u64 t; cvta.to.shared.u64 t, %1; cvt.u32.u64 %0, t; }" : "=r"(a) : "l"(p));
    return a;
}
__device__ __forceinline__ void cp_async16(uint32_t sdst, const void* gsrc) {
    asm volatile("cp.async.cg.shared.global [%0], [%1], 16;" :: "r"(sdst), "l"(gsrc));
}
__device__ __forceinline__ void cp_commit() {
    asm volatile("cp.async.commit_group;");
}
template<int N>
__device__ __forceinline__ void cp_wait() {
    asm volatile("cp.async.wait_group %0;" :: "n"(N));
}
__device__ __forceinline__ void mma_tf32(float& c0, float& c1, float& c2, float& c3,
                                         uint32_t a0, uint32_t a1, uint32_t a2, uint32_t a3,
                                         uint32_t b0, uint32_t b1) {
    asm volatile("mma.sync.aligned.m16n8k8.row.col.f32.tf32.tf32.f32 "
                 "{%0,%1,%2,%3}, {%4,%5,%6,%7}, {%8,%9}, {%0,%1,%2,%3};"
                 : "+f"(c0), "+f"(c1), "+f"(c2), "+f"(c3)
                 : "r"(a0), "r"(a1), "r"(a2), "r"(a3), "r"(b0), "r"(b1));
}

// ---------------------------------------------------------------------------
// Tensor-core GEMM (mma.sync tf32):  C[M,2048] = A[M,2048] @ Bt^T + bias
// CTA tile 128x256, BK=32, 8 warps (2x4), warp tile 64x64.
// round_out=1 -> tf32-round outputs (feeds later tensor-core stages)
// ---------------------------------------------------------------------------
#define GBM 128
#define GBN 256
#define GBK 32
#define SROW 36
#define AS_FLOATS (GBM*SROW)
#define BS_FLOATS (GBN*SROW)
#define STG_FLOATS (AS_FLOATS + BS_FLOATS)
#define GEMM_DSMEM (2*STG_FLOATS*4)
#define NCHUNK (D_MODEL/GBK)

__global__ __launch_bounds__(256, 1)
void gemm_tc(const float* __restrict__ A, const float* __restrict__ Bt,
             const float* __restrict__ bias, float* __restrict__ C, int round_out)
{
    extern __shared__ float smem[];
    const uint32_t smem_base = smem_u32(smem);

    const int tid  = threadIdx.x;
    const int wid  = tid >> 5;
    const int lane = tid & 31;
    const int r    = lane >> 2;
    const int cc   = lane & 3;

    const int m0 = blockIdx.y * GBM;
    const int n0 = blockIdx.x * GBN;
    const int wm = (wid >> 2) * 64;
    const int wn = (wid & 3) * 64;

    const int a_row0 = tid >> 3;
    const int a_seg  = tid & 7;
    const float* Ag = A  + (size_t)(m0 + a_row0) * D_MODEL + a_seg * 4;
    const float* Bg = Bt + (size_t)(n0 + a_row0) * D_MODEL + a_seg * 4;

    float c[4][8][4];
    #pragma unroll
    for (int mi = 0; mi < 4; mi++)
        #pragma unroll
        for (int ni = 0; ni < 8; ni++)
            #pragma unroll
            for (int j = 0; j < 4; j++) c[mi][ni][j] = 0.f;

    auto load_chunk = [&](int chunk, int st) {
        uint32_t as = smem_base + (st*STG_FLOATS) * 4;
        uint32_t bs = as + AS_FLOATS * 4;
        const float* ag = Ag + chunk * GBK;
        const float* bg = Bg + chunk * GBK;
        #pragma unroll
        for (int i = 0; i < 4; i++) {
            int row = a_row0 + i * 32;
            cp_async16(as + (row*SROW + a_seg*4) * 4, ag + (size_t)i*32*D_MODEL);
        }
        #pragma unroll
        for (int i = 0; i < 8; i++) {
            int row = a_row0 + i * 32;
            cp_async16(bs + (row*SROW + a_seg*4) * 4, bg + (size_t)i*32*D_MODEL);
        }
        cp_commit();
    };

    load_chunk(0, 0);
    load_chunk(1, 1);

    for (int ch = 0; ch < NCHUNK; ch++) {
        if (ch == NCHUNK-1) cp_wait<0>(); else cp_wait<1>();
        __syncthreads();

        const float* As = smem + (ch & 1) * STG_FLOATS;
        const float* Bs = As + AS_FLOATS;
        const float* pA = As + (wm + r) * SROW + cc;
        const float* pB = Bs + (wn + r) * SROW + cc;

        #pragma unroll
        for (int ks = 0; ks < 4; ks++) {
            uint32_t a[4][4];
            #pragma unroll
            for (int mi = 0; mi < 4; mi++) {
                const float* p = pA + mi*16*SROW + ks*8;
                a[mi][0] = __float_as_uint(p[0]);
                a[mi][1] = __float_as_uint(p[8*SROW]);
                a[mi][2] = __float_as_uint(p[4]);
                a[mi][3] = __float_as_uint(p[8*SROW + 4]);
            }
            uint32_t b[8][2];
            #pragma unroll
            for (int ni = 0; ni < 8; ni++) {
                const float* p = pB + ni*8*SROW + ks*8;
                b[ni][0] = __float_as_uint(p[0]);
                b[ni][1] = __float_as_uint(p[4]);
            }
            #pragma unroll
            for (int mi = 0; mi < 4; mi++)
                #pragma unroll
                for (int ni = 0; ni < 8; ni++)
                    mma_tf32(c[mi][ni][0], c[mi][ni][1], c[mi][ni][2], c[mi][ni][3],
                             a[mi][0], a[mi][1], a[mi][2], a[mi][3],
                             b[ni][0], b[ni][1]);
        }
        __syncthreads();
        if (ch + 2 < NCHUNK) load_chunk(ch + 2, ch & 1);
    }

    #pragma unroll
    for (int mi = 0; mi < 4; mi++) {
        int row = m0 + wm + mi*16 + r;
        #pragma unroll
        for (int ni = 0; ni < 8; ni++) {
            int col = n0 + wn + ni*8 + cc*2;
            float2 bv = *(const float2*)(bias + col);
            float2 o0, o1;
            o0.x = c[mi][ni][0] + bv.x;  o0.y = c[mi][ni][1] + bv.y;
            o1.x = c[mi][ni][2] + bv.x;  o1.y = c[mi][ni][3] + bv.y;
            if (round_out) {
                o0.x = to_tf32(o0.x); o0.y = to_tf32(o0.y);
                o1.x = to_tf32(o1.x); o1.y = to_tf32(o1.y);
            }
            *(float2*)(C + (size_t)row * D_MODEL + col)     = o0;
            *(float2*)(C + (size_t)(row+8) * D_MODEL + col) = o1;
        }
    }
}

// ---------------------------------------------------------------------------
// Prep kernels
// ---------------------------------------------------------------------------
__global__ void cvt_tf32_kernel(const float4* __restrict__ src, float4* __restrict__ dst, int n4)
{
    int i = blockIdx.x * blockDim.x + threadIdx.x;
    if (i < n4) {
        float4 v = src[i];
        v.x = to_tf32(v.x); v.y = to_tf32(v.y); v.z = to_tf32(v.z); v.w = to_tf32(v.w);
        dst[i] = v;
    }
}

__global__ void transpose_cvt(const float* __restrict__ src, float* __restrict__ dst)
{
    __shared__ float t[32][33];
    int bx = blockIdx.x * 32, by = blockIdx.y * 32;
    int x = bx + threadIdx.x;
    #pragma unroll
    for (int i = 0; i < 32; i += 8)
        t[threadIdx.y + i][threadIdx.x] = src[(size_t)(by + threadIdx.y + i) * D_MODEL + x];
    __syncthreads();
    x = by + threadIdx.x;
    #pragma unroll
    for (int i = 0; i < 32; i += 8)
        dst[(size_t)(bx + threadIdx.y + i) * D_MODEL + x] = to_tf32(t[threadIdx.x][threadIdx.y + i]);
}

// ---------------------------------------------------------------------------
// Tensor-core flash attention (tf32 mma, fp32 online softmax)
// Block: 64 q rows x one (b,h); 4 warps x 16 q rows. KV tiles of 64, 2-stage.
// ---------------------------------------------------------------------------
#define QT 64
#define KT 64
#define NT ((PAST+SEQ)/KT)   // 64
#define SR 132               // Q/K/V smem row stride (floats)
#define PR 68                // P smem row stride
#define OFF_Q     0
#define OFF_K(st) (8448 + (st)*8448)
#define OFF_V(st) (25344 + (st)*8448)
#define OFF_P(w)  (42240 + (w)*1088)
#define ATTN_SMEM_B (46592*4)   // 186368 bytes

__global__ __launch_bounds__(128, 1)
void attn_tc(const float* __restrict__ ck, const float* __restrict__ cv)
{
    extern __shared__ float sm[];
    const uint32_t sbase = smem_u32(sm);
    const int tid  = threadIdx.x;
    const int wid  = tid >> 5;
    const int lane = tid & 31;
    const int r    = lane >> 2;     // 0..7
    const int cc   = lane & 3;      // 0..3
    const int b  = blockIdx.z;
    const int h  = blockIdx.y;
    const int q0 = blockIdx.x * QT;

    // ---- Q load (cp.async group 0)
    {
        const float* qg = g_q + ((size_t)(b*SEQ + q0))*D_MODEL + h*HDIM;
        #pragma unroll
        for (int i = 0; i < 16; i++) {
            int s   = tid + i*128;
            int row = s >> 5, seg = s & 31;
            cp_async16(sbase + (uint32_t)(OFF_Q + row*SR + seg*4)*4,
                       qg + (size_t)row*D_MODEL + seg*4);
        }
        cp_commit();
    }

    auto load_tile = [&](int t, int st) {
        int kv0 = t * KT;
        const float *kb, *vb;
        if (kv0 < PAST) {
            size_t off = ((size_t)(b*PAST + kv0))*D_MODEL + h*HDIM;
            kb = ck + off; vb = cv + off;
        } else {
            size_t off = ((size_t)(b*SEQ + (kv0-PAST)))*D_MODEL + h*HDIM;
            kb = g_k + off; vb = g_v + off;
        }
        #pragma unroll
        for (int i = 0; i < 16; i++) {
            int s   = tid + i*128;
            int row = s >> 5, seg = s & 31;
            cp_async16(sbase + (uint32_t)(OFF_K(st) + row*SR + seg*4)*4,
                       kb + (size_t)row*D_MODEL + seg*4);
            cp_async16(sbase + (uint32_t)(OFF_V(st) + row*SR + seg*4)*4,
                       vb + (size_t)row*D_MODEL + seg*4);
        }
        cp_commit();
    };

    load_tile(0, 0);
    load_tile(1, 1);
    cp_wait<1>();     // Q + tile0 complete
    __syncthreads();

    float o[16][4];
    #pragma unroll
    for (int nj = 0; nj < 16; nj++)
        #pragma unroll
        for (int j = 0; j < 4; j++) o[nj][j] = 0.f;
    float m0 = -1e30f, m1 = -1e30f, l0 = 0.f, l1 = 0.f;

    const float sc = 0.08838834764831845f;   // 1/sqrt(128)
    float* Pw = sm + OFF_P(wid);

    for (int t = 0; t < NT; t++) {
        const float* Ks = sm + OFF_K(t & 1);
        const float* Vs = sm + OFF_V(t & 1);
        const float* pQ = sm + OFF_Q + (wid*16 + r)*SR + cc;
        const float* pK = Ks + r*SR + cc;

        // ---- S = Q @ K^T  (m16 x n64 x k128 per warp)
        float s[8][4];
        #pragma unroll
        for (int ni = 0; ni < 8; ni++)
            #pragma unroll
            for (int j = 0; j < 4; j++) s[ni][j] = 0.f;

        #pragma unroll
        for (int ks = 0; ks < 16; ks++) {
            uint32_t a0 = __float_as_uint(pQ[ks*8]);
            uint32_t a1 = __float_as_uint(pQ[8*SR + ks*8]);
            uint32_t a2 = __float_as_uint(pQ[ks*8 + 4]);
            uint32_t a3 = __float_as_uint(pQ[8*SR + ks*8 + 4]);
            #pragma unroll
            for (int ni = 0; ni < 8; ni++) {
                uint32_t b0 = __float_as_uint(pK[ni*8*SR + ks*8]);
                uint32_t b1 = __float_as_uint(pK[ni*8*SR + ks*8 + 4]);
                mma_tf32(s[ni][0], s[ni][1], s[ni][2], s[ni][3],
                         a0, a1, a2, a3, b0, b1);
            }
        }

        // ---- online softmax (rows r and r+8 of this warp's 16)
        float mx0 = -1e30f, mx1 = -1e30f;
        #pragma unroll
        for (int ni = 0; ni < 8; ni++) {
            s[ni][0] *= sc; s[ni][1] *= sc; s[ni][2] *= sc; s[ni][3] *= sc;
            mx0 = fmaxf(mx0, fmaxf(s[ni][0], s[ni][1]));
            mx1 = fmaxf(mx1, fmaxf(s[ni][2], s[ni][3]));
        }
        mx0 = fmaxf(mx0, __shfl_xor_sync(0xffffffffu, mx0, 1));
        mx0 = fmaxf(mx0, __shfl_xor_sync(0xffffffffu, mx0, 2));
        mx1 = fmaxf(mx1, __shfl_xor_sync(0xffffffffu, mx1, 1));
        mx1 = fmaxf(mx1, __shfl_xor_sync(0xffffffffu, mx1, 2));

        float nm0 = fmaxf(m0, mx0), nm1 = fmaxf(m1, mx1);
        float al0 = __expf(m0 - nm0), al1 = __expf(m1 - nm1);
        float sum0 = 0.f, sum1 = 0.f;
        #pragma unroll
        for (int ni = 0; ni < 8; ni++) {
            s[ni][0] = __expf(s[ni][0] - nm0);
            s[ni][1] = __expf(s[ni][1] - nm0);
            s[ni][2] = __expf(s[ni][2] - nm1);
            s[ni][3] = __expf(s[ni][3] - nm1);
            sum0 += s[ni][0] + s[ni][1];
            sum1 += s[ni][2] + s[ni][3];
        }
        sum0 += __shfl_xor_sync(0xffffffffu, sum0, 1);
        sum0 += __shfl_xor_sync(0xffffffffu, sum0, 2);
        sum1 += __shfl_xor_sync(0xffffffffu, sum1, 1);
        sum1 += __shfl_xor_sync(0xffffffffu, sum1, 2);
        l0 = l0*al0 + sum0;  m0 = nm0;
        l1 = l1*al1 + sum1;  m1 = nm1;

        #pragma unroll
        for (int nj = 0; nj < 16; nj++) {
            o[nj][0] *= al0; o[nj][1] *= al0;
            o[nj][2] *= al1; o[nj][3] *= al1;
        }

        // ---- P to smem (tf32-rounded), warp-private
        #pragma unroll
        for (int ni = 0; ni < 8; ni++) {
            float2 p0, p1;
            p0.x = to_tf32(s[ni][0]); p0.y = to_tf32(s[ni][1]);
            p1.x = to_tf32(s[ni][2]); p1.y = to_tf32(s[ni][3]);
            *(float2*)(Pw + r*PR     + ni*8 + 2*cc) = p0;
            *(float2*)(Pw + (r+8)*PR + ni*8 + 2*cc) = p1;
        }
        __syncwarp();

        // ---- O += P @ V  (m16 x n128 x k64 per warp)
        const float* pP = Pw + r*PR + cc;
        #pragma unroll
        for (int ks = 0; ks < 8; ks++) {
            uint32_t a0 = __float_as_uint(pP[ks*8]);
            uint32_t a1 = __float_as_uint(pP[8*PR + ks*8]);
            uint32_t a2 = __float_as_uint(pP[ks*8 + 4]);
            uint32_t a3 = __float_as_uint(pP[8*PR + ks*8 + 4]);
            const float* pV0 = Vs + (ks*8 + cc)*SR + r;
            const float* pV1 = Vs + (ks*8 + cc + 4)*SR + r;
            #pragma unroll
            for (int nj = 0; nj < 16; nj++) {
                uint32_t b0 = __float_as_uint(pV0[nj*8]);
                uint32_t b1 = __float_as_uint(pV1[nj*8]);
                mma_tf32(o[nj][0], o[nj][1], o[nj][2], o[nj][3],
                         a0, a1, a2, a3, b0, b1);
            }
        }

        __syncthreads();   // all warps done reading stage t&1
        if (t + 1 < NT) {
            if (t + 2 < NT) { load_tile(t + 2, t & 1); cp_wait<1>(); }
            else            cp_wait<0>();
            __syncthreads();
        }
    }

    // ---- epilogue: normalize, tf32-round (feeds out-projection), store
    float il0 = 1.f / l0, il1 = 1.f / l1;
    float* og = g_att + ((size_t)(b*SEQ + q0 + wid*16 + r))*D_MODEL + h*HDIM;
    #pragma unroll
    for (int nj = 0; nj < 16; nj++) {
        float2 v0, v1;
        v0.x = to_tf32(o[nj][0]*il0); v0.y = to_tf32(o[nj][1]*il0);
        v1.x = to_tf32(o[nj][2]*il1); v1.y = to_tf32(o[nj][3]*il1);
        *(float2*)(og + nj*8 + 2*cc)               = v0;
        *(float2*)(og + 8*(size_t)D_MODEL + nj*8 + 2*cc) = v1;
    }
}

// ---------------------------------------------------------------------------
// Launch
// ---------------------------------------------------------------------------
extern "C" void kernel_launch(void* const* d_in, const int* in_sizes, int n_in,
                              void* d_out, int out_size)
{
    (void)in_sizes; (void)n_in; (void)out_size;
    const float* x  = (const float*)d_in[0];
    const float* ck = (const float*)d_in[1];
    const float* cv = (const float*)d_in[2];
    const float* wq = (const float*)d_in[3];
    const float* bq = (const float*)d_in[4];
    const float* wk = (const float*)d_in[5];
    const float* bk = (const float*)d_in[6];
    const float* wv = (const float*)d_in[7];
    const float* bv = (const float*)d_in[8];
    const float* wo = (const float*)d_in[9];
    const float* bo = (const float*)d_in[10];
    float* out = (float*)d_out;

    float *pq, *pk, *pv, *pa, *px, *pw, *pck, *pcv;
    cudaGetSymbolAddress((void**)&pq,  g_q);
    cudaGetSymbolAddress((void**)&pk,  g_k);
    cudaGetSymbolAddress((void**)&pv,  g_v);
    cudaGetSymbolAddress((void**)&pa,  g_att);
    cudaGetSymbolAddress((void**)&px,  g_x32);
    cudaGetSymbolAddress((void**)&pw,  g_wt);
    cudaGetSymbolAddress((void**)&pck, g_ck);
    cudaGetSymbolAddress((void**)&pcv, g_cv);

    float* wt_q = pw + 0*(size_t)D_MODEL*D_MODEL;
    float* wt_k = pw + 1*(size_t)D_MODEL*D_MODEL;
    float* wt_v = pw + 2*(size_t)D_MODEL*D_MODEL;
    float* wt_o = pw + 3*(size_t)D_MODEL*D_MODEL;

    cudaFuncSetAttribute(gemm_tc, cudaFuncAttributeMaxDynamicSharedMemorySize, GEMM_DSMEM);
    cudaFuncSetAttribute(attn_tc, cudaFuncAttributeMaxDynamicSharedMemorySize, ATTN_SMEM_B);

    // Prep: tf32-round x + caches; transpose + tf32-round weights
    int n4x = MROWS*D_MODEL/4;
    int n4c = BATCH*PAST*D_MODEL/4;
    cvt_tf32_kernel<<<(n4x + 255)/256, 256>>>((const float4*)x,  (float4*)px,  n4x);
    cvt_tf32_kernel<<<(n4c + 255)/256, 256>>>((const float4*)ck, (float4*)pck, n4c);
    cvt_tf32_kernel<<<(n4c + 255)/256, 256>>>((const float4*)cv, (float4*)pcv, n4c);
    dim3 tg(D_MODEL/32, D_MODEL/32), tb(32, 8);
    transpose_cvt<<<tg, tb>>>(wq, wt_q);
    transpose_cvt<<<tg, tb>>>(wk, wt_k);
    transpose_cvt<<<tg, tb>>>(wv, wt_v);
    transpose_cvt<<<tg, tb>>>(wo, wt_o);

    // Projections (tensor cores, outputs tf32-rounded for the attention stage)
    dim3 gg(D_MODEL/GBN, MROWS/GBM);
    gemm_tc<<<gg, 256, GEMM_DSMEM>>>(px, wt_q, bq, pq, 1);
    gemm_tc<<<gg, 256, GEMM_DSMEM>>>(px, wt_k, bk, pk, 1);
    gemm_tc<<<gg, 256, GEMM_DSMEM>>>(px, wt_v, bv, pv, 1);

    // Attention (tensor cores)
    dim3 ag(SEQ/QT, NHEAD, BATCH);
    attn_tc<<<ag, 128, ATTN_SMEM_B>>>(pck, pcv);

    // Output projection (fp32 output)
    gemm_tc<<<gg, 256, GEMM_DSMEM>>>(pa, wt_o, bo, out, 0);
}

// round 5
// speedup vs baseline: 8.8076x; 2.1694x over previous
#include <cuda_runtime.h>
#include <cuda_fp16.h>
#include <cstdint>
#include <cstddef>

// Problem constants
#define D_MODEL 2048
#define SEQ     2048
#define PAST    2048
#define NHEAD   16
#define HDIM    128
#define BATCH   2
#define MROWS   (BATCH*SEQ)     // 4096
#define KVTOT   (PAST+SEQ)      // 4096

// Scratch (device globals — allocation-free per harness rules)
__device__ __half g_xh [MROWS*D_MODEL];               // fp16 x
__device__ __half g_q  [MROWS*D_MODEL];
__device__ __half g_k  [MROWS*D_MODEL];
__device__ __half g_v  [MROWS*D_MODEL];
__device__ __half g_att[MROWS*D_MODEL];
__device__ __half g_ck [BATCH*PAST*D_MODEL];          // fp16 cache_k (natural)
__device__ __half g_vt [BATCH*NHEAD*HDIM*KVTOT];      // V transposed per head [hd][kv]
__device__ __half g_wt [4*(size_t)D_MODEL*D_MODEL];   // transposed fp16 weights

// ---------------------------------------------------------------------------
// helpers
// ---------------------------------------------------------------------------
__device__ __forceinline__ uint32_t smem_u32(const void* p) {
    uint32_t a;
    asm("{ .reg .u64 t; cvta.to.shared.u64 t, %1; cvt.u32.u64 %0, t; }" : "=r"(a) : "l"(p));
    return a;
}
__device__ __forceinline__ void cp_async16(uint32_t sdst, const void* gsrc) {
    asm volatile("cp.async.cg.shared.global [%0], [%1], 16;" :: "r"(sdst), "l"(gsrc));
}
__device__ __forceinline__ void cp_commit() {
    asm volatile("cp.async.commit_group;");
}
template<int N>
__device__ __forceinline__ void cp_wait() {
    asm volatile("cp.async.wait_group %0;" :: "n"(N));
}
// fp16 MMA, fp32 accumulate: m16n8k16
__device__ __forceinline__ void mma_h(float& c0, float& c1, float& c2, float& c3,
                                      uint32_t a0, uint32_t a1, uint32_t a2, uint32_t a3,
                                      uint32_t b0, uint32_t b1) {
    asm volatile("mma.sync.aligned.m16n8k16.row.col.f32.f16.f16.f32 "
                 "{%0,%1,%2,%3}, {%4,%5,%6,%7}, {%8,%9}, {%0,%1,%2,%3};"
                 : "+f"(c0), "+f"(c1), "+f"(c2), "+f"(c3)
                 : "r"(a0), "r"(a1), "r"(a2), "r"(a3), "r"(b0), "r"(b1));
}

// ---------------------------------------------------------------------------
// fp16 GEMM: C[M,2048] = A[M,2048] @ Bt^T + bias.  A,Bt half K-major.
// CTA 128x256, BK=64, 8 warps (2x4), warp tile 64x64. half_out: 1=half C, 0=fp32 C.
// ---------------------------------------------------------------------------
#define GBM 128
#define GBN 256
#define GBK 64
#define SWH 72                      // smem row stride in halfs
#define AS_H (GBM*SWH)              // 9216 halfs
#define BS_H (GBN*SWH)              // 18432 halfs
#define STG_H (AS_H+BS_H)           // 27648 halfs
#define GEMM_DSMEM (2*STG_H*2)      // 110592 bytes
#define NCHUNK (D_MODEL/GBK)        // 32

__global__ __launch_bounds__(256, 1)
void gemm_h(const __half* __restrict__ A, const __half* __restrict__ Bt,
            const float* __restrict__ bias, void* __restrict__ Cout, int half_out)
{
    extern __shared__ __half sh[];
    const uint32_t sbase = smem_u32(sh);

    const int tid  = threadIdx.x;
    const int wid  = tid >> 5;
    const int lane = tid & 31;
    const int r    = lane >> 2;       // 0..7
    const int cc   = lane & 3;        // 0..3

    const int m0 = blockIdx.y * GBM;
    const int n0 = blockIdx.x * GBN;
    const int wm = (wid >> 2) * 64;
    const int wn = (wid & 3) * 64;

    // gmem->smem: 16B segments (8 halfs). A: 128 rows x 8 segs; B: 256 rows x 8 segs
    const int row8 = tid >> 3;        // 0..31
    const int seg  = tid & 7;         // 0..7
    const __half* Ag = A  + (size_t)(m0 + row8) * D_MODEL + seg * 8;
    const __half* Bg = Bt + (size_t)(n0 + row8) * D_MODEL + seg * 8;

    float c[4][8][4];
    #pragma unroll
    for (int mi = 0; mi < 4; mi++)
        #pragma unroll
        for (int ni = 0; ni < 8; ni++)
            #pragma unroll
            for (int j = 0; j < 4; j++) c[mi][ni][j] = 0.f;

    auto load_chunk = [&](int chunk, int st) {
        uint32_t as = sbase + (st*STG_H) * 2;
        uint32_t bs = as + AS_H * 2;
        const __half* ag = Ag + chunk * GBK;
        const __half* bg = Bg + chunk * GBK;
        #pragma unroll
        for (int i = 0; i < 4; i++) {
            int row = row8 + i * 32;
            cp_async16(as + (uint32_t)(row*SWH + seg*8)*2, ag + (size_t)i*32*D_MODEL);
        }
        #pragma unroll
        for (int i = 0; i < 8; i++) {
            int row = row8 + i * 32;
            cp_async16(bs + (uint32_t)(row*SWH + seg*8)*2, bg + (size_t)i*32*D_MODEL);
        }
        cp_commit();
    };

    load_chunk(0, 0);
    load_chunk(1, 1);

    for (int ch = 0; ch < NCHUNK; ch++) {
        if (ch == NCHUNK-1) cp_wait<0>(); else cp_wait<1>();
        __syncthreads();

        const uint32_t* As32 = (const uint32_t*)(sh + (ch & 1) * STG_H);
        const uint32_t* Bs32 = As32 + AS_H/2;
        const uint32_t* pA = As32 + (wm + r) * (SWH/2) + cc;
        const uint32_t* pB = Bs32 + (wn + r) * (SWH/2) + cc;

        #pragma unroll
        for (int ks = 0; ks < 4; ks++) {
            uint32_t a[4][4];
            #pragma unroll
            for (int mi = 0; mi < 4; mi++) {
                const uint32_t* p = pA + mi*16*(SWH/2) + ks*8;
                a[mi][0] = p[0];
                a[mi][1] = p[8*(SWH/2)];
                a[mi][2] = p[4];
                a[mi][3] = p[8*(SWH/2) + 4];
            }
            uint32_t b[8][2];
            #pragma unroll
            for (int ni = 0; ni < 8; ni++) {
                const uint32_t* p = pB + ni*8*(SWH/2) + ks*8;
                b[ni][0] = p[0];
                b[ni][1] = p[4];
            }
            #pragma unroll
            for (int mi = 0; mi < 4; mi++)
                #pragma unroll
                for (int ni = 0; ni < 8; ni++)
                    mma_h(c[mi][ni][0], c[mi][ni][1], c[mi][ni][2], c[mi][ni][3],
                          a[mi][0], a[mi][1], a[mi][2], a[mi][3],
                          b[ni][0], b[ni][1]);
        }
        __syncthreads();
        if (ch + 2 < NCHUNK) load_chunk(ch + 2, ch & 1);
    }

    #pragma unroll
    for (int mi = 0; mi < 4; mi++) {
        int row = m0 + wm + mi*16 + r;
        #pragma unroll
        for (int ni = 0; ni < 8; ni++) {
            int col = n0 + wn + ni*8 + cc*2;
            float2 bv = *(const float2*)(bias + col);
            float o00 = c[mi][ni][0] + bv.x, o01 = c[mi][ni][1] + bv.y;
            float o10 = c[mi][ni][2] + bv.x, o11 = c[mi][ni][3] + bv.y;
            if (half_out) {
                __half* Ch = (__half*)Cout;
                *(__half2*)(Ch + (size_t)row*D_MODEL + col)     = __floats2half2_rn(o00, o01);
                *(__half2*)(Ch + (size_t)(row+8)*D_MODEL + col) = __floats2half2_rn(o10, o11);
            } else {
                float* Cf = (float*)Cout;
                *(float2*)(Cf + (size_t)row*D_MODEL + col)     = make_float2(o00, o01);
                *(float2*)(Cf + (size_t)(row+8)*D_MODEL + col) = make_float2(o10, o11);
            }
        }
    }
}

// ---------------------------------------------------------------------------
// Prep kernels
// ---------------------------------------------------------------------------
__global__ void cvt_h(const float* __restrict__ src, __half* __restrict__ dst, int n)
{
    int i = (blockIdx.x * blockDim.x + threadIdx.x) * 8;
    if (i < n) {
        float4 f0 = *(const float4*)(src + i);
        float4 f1 = *(const float4*)(src + i + 4);
        __half2 h[4];
        h[0] = __floats2half2_rn(f0.x, f0.y);
        h[1] = __floats2half2_rn(f0.z, f0.w);
        h[2] = __floats2half2_rn(f1.x, f1.y);
        h[3] = __floats2half2_rn(f1.z, f1.w);
        *(uint4*)(dst + i) = *(const uint4*)h;
    }
}

// weight transpose fp32 [K][N] -> half [N][K]
__global__ void transpose_w_h(const float* __restrict__ src, __half* __restrict__ dst)
{
    __shared__ float t[32][33];
    int bx = blockIdx.x * 32, by = blockIdx.y * 32;
    int x = bx + threadIdx.x;
    #pragma unroll
    for (int i = 0; i < 32; i += 8)
        t[threadIdx.y + i][threadIdx.x] = src[(size_t)(by + threadIdx.y + i) * D_MODEL + x];
    __syncthreads();
    x = by + threadIdx.x;
    #pragma unroll
    for (int i = 0; i < 32; i += 8)
        dst[(size_t)(bx + threadIdx.y + i) * D_MODEL + x] = __float2half(t[threadIdx.x][threadIdx.y + i]);
}

// cache_v fp32 [b][p][D] -> g_vt half [(b*16+h)*128+hd][KVTOT] at col p
__global__ void transpose_vc(const float* __restrict__ cv, __half* __restrict__ vt)
{
    __shared__ float t[32][33];
    int p0 = blockIdx.x * 32, d0 = blockIdx.y * 32, b = blockIdx.z;
    #pragma unroll
    for (int i = 0; i < 32; i += 8)
        t[threadIdx.y + i][threadIdx.x] =
            cv[((size_t)b*PAST + p0 + threadIdx.y + i) * D_MODEL + d0 + threadIdx.x];
    __syncthreads();
    #pragma unroll
    for (int i = 0; i < 32; i += 8) {
        int d  = d0 + threadIdx.y + i;
        int h  = d >> 7, hd = d & 127;
        vt[((size_t)((b*NHEAD + h)*HDIM + hd)) * KVTOT + p0 + threadIdx.x] =
            __float2half(t[threadIdx.x][threadIdx.y + i]);
    }
}

// v_new half [b][s][D] -> g_vt at col PAST+s
__global__ void transpose_vn(const __half* __restrict__ v, __half* __restrict__ vt)
{
    __shared__ __half t[32][34];
    int s0 = blockIdx.x * 32, d0 = blockIdx.y * 32, b = blockIdx.z;
    #pragma unroll
    for (int i = 0; i < 32; i += 8)
        t[threadIdx.y + i][threadIdx.x] =
            v[((size_t)b*SEQ + s0 + threadIdx.y + i) * D_MODEL + d0 + threadIdx.x];
    __syncthreads();
    #pragma unroll
    for (int i = 0; i < 32; i += 8) {
        int d  = d0 + threadIdx.y + i;
        int h  = d >> 7, hd = d & 127;
        vt[((size_t)((b*NHEAD + h)*HDIM + hd)) * KVTOT + PAST + s0 + threadIdx.x] =
            t[threadIdx.x][threadIdx.y + i];
    }
}

// ---------------------------------------------------------------------------
// fp16 tensor-core flash attention. Block: 64 q rows x (b,h); 4 warps x 16 rows.
// KV tiles of 64, double-buffered. K natural [kv][hd]; V transposed [hd][kv].
// ---------------------------------------------------------------------------
#define QT 64
#define KT 64
#define NT (KVTOT/KT)          // 64
#define SQH 136                // Q/K smem row stride (halfs)
#define SVH 72                 // Vt smem row stride (halfs)
#define PRH 72                 // P row stride (halfs)
// offsets in halfs
#define OFF_Q      0
#define OFF_K(st)  (8704 + (st)*8704)        // 64*136
#define OFF_VT(st) (26112 + (st)*9216)       // 128*72
#define OFF_P(w)   (44544 + (w)*1152)        // 16*72
#define ATTN_SMEM_H ((44544 + 4*1152)*2)     // 98304 bytes

__global__ __launch_bounds__(128, 1)
void attn_h(const __half* __restrict__ ck)
{
    extern __shared__ __half sm[];
    const uint32_t sbase = smem_u32(sm);
    const int tid  = threadIdx.x;
    const int wid  = tid >> 5;
    const int lane = tid & 31;
    const int r    = lane >> 2;
    const int cc   = lane & 3;
    const int b  = blockIdx.z;
    const int h  = blockIdx.y;
    const int q0 = blockIdx.x * QT;

    const __half* vt_head = g_vt + ((size_t)((b*NHEAD + h)*HDIM)) * KVTOT;

    // Q load (group 0): 64 rows x 128 halfs = 1024 segs of 16B
    {
        const __half* qg = g_q + ((size_t)(b*SEQ + q0))*D_MODEL + h*HDIM;
        #pragma unroll
        for (int i = 0; i < 8; i++) {
            int s = tid + i*128;
            int row = s >> 4, seg = s & 15;
            cp_async16(sbase + (uint32_t)(OFF_Q + row*SQH + seg*8)*2,
                       qg + (size_t)row*D_MODEL + seg*8);
        }
        cp_commit();
    }

    auto load_tile = [&](int t, int st) {
        int kv0 = t * KT;
        const __half* kb;
        if (kv0 < PAST) kb = ck  + ((size_t)(b*PAST + kv0))*D_MODEL + h*HDIM;
        else            kb = g_k + ((size_t)(b*SEQ + (kv0-PAST)))*D_MODEL + h*HDIM;
        #pragma unroll
        for (int i = 0; i < 8; i++) {   // K: 64 rows x 16 segs
            int s = tid + i*128;
            int row = s >> 4, seg = s & 15;
            cp_async16(sbase + (uint32_t)(OFF_K(st) + row*SQH + seg*8)*2,
                       kb + (size_t)row*D_MODEL + seg*8);
        }
        #pragma unroll
        for (int i = 0; i < 8; i++) {   // Vt: 128 rows x 8 segs
            int s = tid + i*128;
            int row = s >> 3, seg = s & 7;
            cp_async16(sbase + (uint32_t)(OFF_VT(st) + row*SVH + seg*8)*2,
                       vt_head + (size_t)row*KVTOT + kv0 + seg*8);
        }
        cp_commit();
    };

    load_tile(0, 0);
    load_tile(1, 1);
    cp_wait<1>();
    __syncthreads();

    float o[16][4];
    #pragma unroll
    for (int nj = 0; nj < 16; nj++)
        #pragma unroll
        for (int j = 0; j < 4; j++) o[nj][j] = 0.f;
    float m0 = -1e30f, m1 = -1e30f, l0 = 0.f, l1 = 0.f;

    const float sc = 0.08838834764831845f;   // 1/sqrt(128)
    uint32_t* Pw32 = (uint32_t*)(sm + OFF_P(wid));

    for (int t = 0; t < NT; t++) {
        const uint32_t* K32  = (const uint32_t*)(sm + OFF_K(t & 1));
        const uint32_t* Vt32 = (const uint32_t*)(sm + OFF_VT(t & 1));
        const uint32_t* pQ   = (const uint32_t*)(sm + OFF_Q) + (wid*16 + r)*(SQH/2) + cc;
        const uint32_t* pK   = K32 + r*(SQH/2) + cc;

        // ---- S = Q @ K^T (m16 n64 k128)
        float s[8][4];
        #pragma unroll
        for (int ni = 0; ni < 8; ni++)
            #pragma unroll
            for (int j = 0; j < 4; j++) s[ni][j] = 0.f;

        #pragma unroll
        for (int ks = 0; ks < 8; ks++) {
            uint32_t a0 = pQ[ks*8];
            uint32_t a1 = pQ[8*(SQH/2) + ks*8];
            uint32_t a2 = pQ[ks*8 + 4];
            uint32_t a3 = pQ[8*(SQH/2) + ks*8 + 4];
            #pragma unroll
            for (int ni = 0; ni < 8; ni++) {
                uint32_t b0 = pK[ni*8*(SQH/2) + ks*8];
                uint32_t b1 = pK[ni*8*(SQH/2) + ks*8 + 4];
                mma_h(s[ni][0], s[ni][1], s[ni][2], s[ni][3],
                      a0, a1, a2, a3, b0, b1);
            }
        }

        // ---- online softmax (rows r and r+8)
        float mx0 = -1e30f, mx1 = -1e30f;
        #pragma unroll
        for (int ni = 0; ni < 8; ni++) {
            s[ni][0] *= sc; s[ni][1] *= sc; s[ni][2] *= sc; s[ni][3] *= sc;
            mx0 = fmaxf(mx0, fmaxf(s[ni][0], s[ni][1]));
            mx1 = fmaxf(mx1, fmaxf(s[ni][2], s[ni][3]));
        }
        mx0 = fmaxf(mx0, __shfl_xor_sync(0xffffffffu, mx0, 1));
        mx0 = fmaxf(mx0, __shfl_xor_sync(0xffffffffu, mx0, 2));
        mx1 = fmaxf(mx1, __shfl_xor_sync(0xffffffffu, mx1, 1));
        mx1 = fmaxf(mx1, __shfl_xor_sync(0xffffffffu, mx1, 2));

        float nm0 = fmaxf(m0, mx0), nm1 = fmaxf(m1, mx1);
        float al0 = __expf(m0 - nm0), al1 = __expf(m1 - nm1);
        float sum0 = 0.f, sum1 = 0.f;
        #pragma unroll
        for (int ni = 0; ni < 8; ni++) {
            s[ni][0] = __expf(s[ni][0] - nm0);
            s[ni][1] = __expf(s[ni][1] - nm0);
            s[ni][2] = __expf(s[ni][2] - nm1);
            s[ni][3] = __expf(s[ni][3] - nm1);
            sum0 += s[ni][0] + s[ni][1];
            sum1 += s[ni][2] + s[ni][3];
        }
        sum0 += __shfl_xor_sync(0xffffffffu, sum0, 1);
        sum0 += __shfl_xor_sync(0xffffffffu, sum0, 2);
        sum1 += __shfl_xor_sync(0xffffffffu, sum1, 1);
        sum1 += __shfl_xor_sync(0xffffffffu, sum1, 2);
        l0 = l0*al0 + sum0;  m0 = nm0;
        l1 = l1*al1 + sum1;  m1 = nm1;

        #pragma unroll
        for (int nj = 0; nj < 16; nj++) {
            o[nj][0] *= al0; o[nj][1] *= al0;
            o[nj][2] *= al1; o[nj][3] *= al1;
        }

        // ---- P to smem (fp16), warp-private [16][64]
        #pragma unroll
        for (int ni = 0; ni < 8; ni++) {
            __half2 p0 = __floats2half2_rn(s[ni][0], s[ni][1]);
            __half2 p1 = __floats2half2_rn(s[ni][2], s[ni][3]);
            Pw32[r*(PRH/2)     + ni*4 + cc] = *(uint32_t*)&p0;
            Pw32[(r+8)*(PRH/2) + ni*4 + cc] = *(uint32_t*)&p1;
        }
        __syncwarp();

        // ---- O += P @ V  (m16 n128 k64); B from Vt [hd][kv]
        const uint32_t* pP = Pw32 + r*(PRH/2) + cc;
        #pragma unroll
        for (int ks = 0; ks < 4; ks++) {
            uint32_t a0 = pP[ks*8];
            uint32_t a1 = pP[8*(PRH/2) + ks*8];
            uint32_t a2 = pP[ks*8 + 4];
            uint32_t a3 = pP[8*(PRH/2) + ks*8 + 4];
            #pragma unroll
            for (int nj = 0; nj < 16; nj++) {
                uint32_t b0 = Vt32[(nj*8 + r)*(SVH/2) + ks*8 + cc];
                uint32_t b1 = Vt32[(nj*8 + r)*(SVH/2) + ks*8 + cc + 4];
                mma_h(o[nj][0], o[nj][1], o[nj][2], o[nj][3],
                      a0, a1, a2, a3, b0, b1);
            }
        }

        __syncthreads();
        if (t + 1 < NT) {
            if (t + 2 < NT) { load_tile(t + 2, t & 1); cp_wait<1>(); }
            else            cp_wait<0>();
            __syncthreads();
        }
    }

    // ---- epilogue: normalize, store fp16 (feeds out-projection)
    float il0 = 1.f / l0, il1 = 1.f / l1;
    __half* og = g_att + ((size_t)(b*SEQ + q0 + wid*16 + r))*D_MODEL + h*HDIM;
    #pragma unroll
    for (int nj = 0; nj < 16; nj++) {
        __half2 v0 = __floats2half2_rn(o[nj][0]*il0, o[nj][1]*il0);
        __half2 v1 = __floats2half2_rn(o[nj][2]*il1, o[nj][3]*il1);
        *(__half2*)(og + nj*8 + 2*cc)                     = v0;
        *(__half2*)(og + 8*(size_t)D_MODEL + nj*8 + 2*cc) = v1;
    }
}

// ---------------------------------------------------------------------------
// Launch
// ---------------------------------------------------------------------------
extern "C" void kernel_launch(void* const* d_in, const int* in_sizes, int n_in,
                              void* d_out, int out_size)
{
    (void)in_sizes; (void)n_in; (void)out_size;
    const float* x  = (const float*)d_in[0];
    const float* ck = (const float*)d_in[1];
    const float* cv = (const float*)d_in[2];
    const float* wq = (const float*)d_in[3];
    const float* bq = (const float*)d_in[4];
    const float* wk = (const float*)d_in[5];
    const float* bk = (const float*)d_in[6];
    const float* wv = (const float*)d_in[7];
    const float* bv = (const float*)d_in[8];
    const float* wo = (const float*)d_in[9];
    const float* bo = (const float*)d_in[10];
    float* out = (float*)d_out;

    __half *pxh, *pq, *pk, *pv, *pa, *pckh, *pvt, *pw;
    cudaGetSymbolAddress((void**)&pxh,  g_xh);
    cudaGetSymbolAddress((void**)&pq,   g_q);
    cudaGetSymbolAddress((void**)&pk,   g_k);
    cudaGetSymbolAddress((void**)&pv,   g_v);
    cudaGetSymbolAddress((void**)&pa,   g_att);
    cudaGetSymbolAddress((void**)&pckh, g_ck);
    cudaGetSymbolAddress((void**)&pvt,  g_vt);
    cudaGetSymbolAddress((void**)&pw,   g_wt);

    __half* wt_q = pw + 0*(size_t)D_MODEL*D_MODEL;
    __half* wt_k = pw + 1*(size_t)D_MODEL*D_MODEL;
    __half* wt_v = pw + 2*(size_t)D_MODEL*D_MODEL;
    __half* wt_o = pw + 3*(size_t)D_MODEL*D_MODEL;

    cudaFuncSetAttribute(gemm_h, cudaFuncAttributeMaxDynamicSharedMemorySize, GEMM_DSMEM);
    cudaFuncSetAttribute(attn_h, cudaFuncAttributeMaxDynamicSharedMemorySize, ATTN_SMEM_H);

    // Prep: fp16 conversions + transposes
    int nx = MROWS*D_MODEL;
    int nc = BATCH*PAST*D_MODEL;
    cvt_h<<<(nx/8 + 255)/256, 256>>>(x,  pxh,  nx);
    cvt_h<<<(nc/8 + 255)/256, 256>>>(ck, pckh, nc);
    dim3 tb(32, 8);
    dim3 tgw(D_MODEL/32, D_MODEL/32);
    transpose_w_h<<<tgw, tb>>>(wq, wt_q);
    transpose_w_h<<<tgw, tb>>>(wk, wt_k);
    transpose_w_h<<<tgw, tb>>>(wv, wt_v);
    transpose_w_h<<<tgw, tb>>>(wo, wt_o);
    dim3 tgv(PAST/32, D_MODEL/32, BATCH);
    transpose_vc<<<tgv, tb>>>(cv, pvt);

    // Projections (fp16 tensor cores, fp16 outputs)
    dim3 gg(D_MODEL/GBN, MROWS/GBM);
    gemm_h<<<gg, 256, GEMM_DSMEM>>>(pxh, wt_q, bq, pq, 1);
    gemm_h<<<gg, 256, GEMM_DSMEM>>>(pxh, wt_k, bk, pk, 1);
    gemm_h<<<gg, 256, GEMM_DSMEM>>>(pxh, wt_v, bv, pv, 1);

    // v_new -> transposed layout
    dim3 tgn(SEQ/32, D_MODEL/32, BATCH);
    transpose_vn<<<tgn, tb>>>(pv, pvt);

    // Attention (fp16 tensor cores)
    dim3 ag(SEQ/QT, NHEAD, BATCH);
    attn_h<<<ag, 128, ATTN_SMEM_H>>>(pckh);

    // Output projection (fp32 out)
    gemm_h<<<gg, 256, GEMM_DSMEM>>>(pa, wt_o, bo, out, 0);
}

// round 6
// speedup vs baseline: 9.0479x; 1.0273x over previous
#include <cuda_runtime.h>
#include <cuda_fp16.h>
#include <cstdint>
#include <cstddef>

// Problem constants
#define D_MODEL 2048
#define SEQ     2048
#define PAST    2048
#define NHEAD   16
#define HDIM    128
#define BATCH   2
#define MROWS   (BATCH*SEQ)     // 4096
#define KVTOT   (PAST+SEQ)      // 4096
#define NQT     (SEQ/64)        // 32 q-tiles per (b,h)

// Scratch (device globals — allocation-free per harness rules)
__device__ __half g_xh [MROWS*D_MODEL];               // fp16 x
__device__ __half g_q  [MROWS*D_MODEL];
__device__ __half g_k  [MROWS*D_MODEL];
__device__ __half g_v  [MROWS*D_MODEL];
__device__ __half g_att[MROWS*D_MODEL];
__device__ __half g_ck [BATCH*PAST*D_MODEL];          // fp16 cache_k (natural)
__device__ __half g_vt [BATCH*NHEAD*HDIM*KVTOT];      // V transposed per head [hd][kv]
__device__ __half g_wt [4*(size_t)D_MODEL*D_MODEL];   // transposed fp16 weights
// split-KV partials: [half][b][h][qt][64 rows][128 cols]
__device__ float  g_po [2*BATCH*NHEAD*NQT*64*128];    // 134 MB
__device__ float  g_pm [2*BATCH*NHEAD*NQT*64];
__device__ float  g_pl [2*BATCH*NHEAD*NQT*64];

// ---------------------------------------------------------------------------
// helpers
// ---------------------------------------------------------------------------
__device__ __forceinline__ uint32_t smem_u32(const void* p) {
    uint32_t a;
    asm("{ .reg .u64 t; cvta.to.shared.u64 t, %1; cvt.u32.u64 %0, t; }" : "=r"(a) : "l"(p));
    return a;
}
__device__ __forceinline__ void cp_async16(uint32_t sdst, const void* gsrc) {
    asm volatile("cp.async.cg.shared.global [%0], [%1], 16;" :: "r"(sdst), "l"(gsrc));
}
__device__ __forceinline__ void cp_commit() {
    asm volatile("cp.async.commit_group;");
}
template<int N>
__device__ __forceinline__ void cp_wait() {
    asm volatile("cp.async.wait_group %0;" :: "n"(N));
}
// fp16 MMA, fp32 accumulate: m16n8k16
__device__ __forceinline__ void mma_h(float& c0, float& c1, float& c2, float& c3,
                                      uint32_t a0, uint32_t a1, uint32_t a2, uint32_t a3,
                                      uint32_t b0, uint32_t b1) {
    asm volatile("mma.sync.aligned.m16n8k16.row.col.f32.f16.f16.f32 "
                 "{%0,%1,%2,%3}, {%4,%5,%6,%7}, {%8,%9}, {%0,%1,%2,%3};"
                 : "+f"(c0), "+f"(c1), "+f"(c2), "+f"(c3)
                 : "r"(a0), "r"(a1), "r"(a2), "r"(a3), "r"(b0), "r"(b1));
}

// ---------------------------------------------------------------------------
// fp16 GEMM: C[M,2048] = A[M,2048] @ Bt^T + bias.  3-stage cp.async pipeline.
// CTA 128x256, BK=64, 8 warps (2x4), warp tile 64x64.
// ---------------------------------------------------------------------------
#define GBM 128
#define GBN 256
#define GBK 64
#define SWH 72
#define AS_H (GBM*SWH)
#define BS_H (GBN*SWH)
#define STG_H (AS_H+BS_H)           // 27648 halfs
#define GSTG 3
#define GEMM_DSMEM (GSTG*STG_H*2)   // 165888 bytes
#define NCHUNK (D_MODEL/GBK)        // 32

__global__ __launch_bounds__(256, 1)
void gemm_h(const __half* __restrict__ A, const __half* __restrict__ Bt,
            const float* __restrict__ bias, void* __restrict__ Cout, int half_out)
{
    extern __shared__ __half sh[];
    const uint32_t sbase = smem_u32(sh);

    const int tid  = threadIdx.x;
    const int wid  = tid >> 5;
    const int lane = tid & 31;
    const int r    = lane >> 2;
    const int cc   = lane & 3;

    const int m0 = blockIdx.y * GBM;
    const int n0 = blockIdx.x * GBN;
    const int wm = (wid >> 2) * 64;
    const int wn = (wid & 3) * 64;

    const int row8 = tid >> 3;
    const int seg  = tid & 7;
    const __half* Ag = A  + (size_t)(m0 + row8) * D_MODEL + seg * 8;
    const __half* Bg = Bt + (size_t)(n0 + row8) * D_MODEL + seg * 8;

    float c[4][8][4];
    #pragma unroll
    for (int mi = 0; mi < 4; mi++)
        #pragma unroll
        for (int ni = 0; ni < 8; ni++)
            #pragma unroll
            for (int j = 0; j < 4; j++) c[mi][ni][j] = 0.f;

    auto load_chunk = [&](int chunk, int st) {
        uint32_t as = sbase + (st*STG_H) * 2;
        uint32_t bs = as + AS_H * 2;
        const __half* ag = Ag + chunk * GBK;
        const __half* bg = Bg + chunk * GBK;
        #pragma unroll
        for (int i = 0; i < 4; i++) {
            int row = row8 + i * 32;
            cp_async16(as + (uint32_t)(row*SWH + seg*8)*2, ag + (size_t)i*32*D_MODEL);
        }
        #pragma unroll
        for (int i = 0; i < 8; i++) {
            int row = row8 + i * 32;
            cp_async16(bs + (uint32_t)(row*SWH + seg*8)*2, bg + (size_t)i*32*D_MODEL);
        }
        cp_commit();
    };

    load_chunk(0, 0);
    load_chunk(1, 1);
    load_chunk(2, 2);

    for (int ch = 0; ch < NCHUNK; ch++) {
        int rem = NCHUNK - 1 - ch;
        if (rem >= 2)      cp_wait<2>();
        else if (rem == 1) cp_wait<1>();
        else               cp_wait<0>();
        __syncthreads();

        int st = ch % GSTG;
        const uint32_t* As32 = (const uint32_t*)(sh + st * STG_H);
        const uint32_t* Bs32 = As32 + AS_H/2;
        const uint32_t* pA = As32 + (wm + r) * (SWH/2) + cc;
        const uint32_t* pB = Bs32 + (wn + r) * (SWH/2) + cc;

        #pragma unroll
        for (int ks = 0; ks < 4; ks++) {
            uint32_t a[4][4];
            #pragma unroll
            for (int mi = 0; mi < 4; mi++) {
                const uint32_t* p = pA + mi*16*(SWH/2) + ks*8;
                a[mi][0] = p[0];
                a[mi][1] = p[8*(SWH/2)];
                a[mi][2] = p[4];
                a[mi][3] = p[8*(SWH/2) + 4];
            }
            uint32_t b[8][2];
            #pragma unroll
            for (int ni = 0; ni < 8; ni++) {
                const uint32_t* p = pB + ni*8*(SWH/2) + ks*8;
                b[ni][0] = p[0];
                b[ni][1] = p[4];
            }
            #pragma unroll
            for (int mi = 0; mi < 4; mi++)
                #pragma unroll
                for (int ni = 0; ni < 8; ni++)
                    mma_h(c[mi][ni][0], c[mi][ni][1], c[mi][ni][2], c[mi][ni][3],
                          a[mi][0], a[mi][1], a[mi][2], a[mi][3],
                          b[ni][0], b[ni][1]);
        }
        __syncthreads();
        if (ch + GSTG < NCHUNK) load_chunk(ch + GSTG, st);
    }

    #pragma unroll
    for (int mi = 0; mi < 4; mi++) {
        int row = m0 + wm + mi*16 + r;
        #pragma unroll
        for (int ni = 0; ni < 8; ni++) {
            int col = n0 + wn + ni*8 + cc*2;
            float2 bv = *(const float2*)(bias + col);
            float o00 = c[mi][ni][0] + bv.x, o01 = c[mi][ni][1] + bv.y;
            float o10 = c[mi][ni][2] + bv.x, o11 = c[mi][ni][3] + bv.y;
            if (half_out) {
                __half* Ch = (__half*)Cout;
                *(__half2*)(Ch + (size_t)row*D_MODEL + col)     = __floats2half2_rn(o00, o01);
                *(__half2*)(Ch + (size_t)(row+8)*D_MODEL + col) = __floats2half2_rn(o10, o11);
            } else {
                float* Cf = (float*)Cout;
                *(float2*)(Cf + (size_t)row*D_MODEL + col)     = make_float2(o00, o01);
                *(float2*)(Cf + (size_t)(row+8)*D_MODEL + col) = make_float2(o10, o11);
            }
        }
    }
}

// ---------------------------------------------------------------------------
// Prep kernels
// ---------------------------------------------------------------------------
__global__ void cvt_h(const float* __restrict__ src, __half* __restrict__ dst, int n)
{
    int i = (blockIdx.x * blockDim.x + threadIdx.x) * 8;
    if (i < n) {
        float4 f0 = *(const float4*)(src + i);
        float4 f1 = *(const float4*)(src + i + 4);
        __half2 h[4];
        h[0] = __floats2half2_rn(f0.x, f0.y);
        h[1] = __floats2half2_rn(f0.z, f0.w);
        h[2] = __floats2half2_rn(f1.x, f1.y);
        h[3] = __floats2half2_rn(f1.z, f1.w);
        *(uint4*)(dst + i) = *(const uint4*)h;
    }
}

// all four weights transposed in one launch (z selects the matrix)
__global__ void transpose_w4(const float* __restrict__ w0, const float* __restrict__ w1,
                             const float* __restrict__ w2, const float* __restrict__ w3,
                             __half* __restrict__ dstBase)
{
    __shared__ float t[32][33];
    const float* src = (blockIdx.z == 0) ? w0 : (blockIdx.z == 1) ? w1 :
                       (blockIdx.z == 2) ? w2 : w3;
    __half* dst = dstBase + (size_t)blockIdx.z * D_MODEL * D_MODEL;
    int bx = blockIdx.x * 32, by = blockIdx.y * 32;
    int x = bx + threadIdx.x;
    #pragma unroll
    for (int i = 0; i < 32; i += 8)
        t[threadIdx.y + i][threadIdx.x] = src[(size_t)(by + threadIdx.y + i) * D_MODEL + x];
    __syncthreads();
    x = by + threadIdx.x;
    #pragma unroll
    for (int i = 0; i < 32; i += 8)
        dst[(size_t)(bx + threadIdx.y + i) * D_MODEL + x] = __float2half(t[threadIdx.x][threadIdx.y + i]);
}

// cache_v fp32 [b][p][D] -> g_vt half [(b*16+h)*128+hd][KVTOT] at col p
__global__ void transpose_vc(const float* __restrict__ cv, __half* __restrict__ vt)
{
    __shared__ float t[32][33];
    int p0 = blockIdx.x * 32, d0 = blockIdx.y * 32, b = blockIdx.z;
    #pragma unroll
    for (int i = 0; i < 32; i += 8)
        t[threadIdx.y + i][threadIdx.x] =
            cv[((size_t)b*PAST + p0 + threadIdx.y + i) * D_MODEL + d0 + threadIdx.x];
    __syncthreads();
    #pragma unroll
    for (int i = 0; i < 32; i += 8) {
        int d  = d0 + threadIdx.y + i;
        int h  = d >> 7, hd = d & 127;
        vt[((size_t)((b*NHEAD + h)*HDIM + hd)) * KVTOT + p0 + threadIdx.x] =
            __float2half(t[threadIdx.x][threadIdx.y + i]);
    }
}

// v_new half [b][s][D] -> g_vt at col PAST+s
__global__ void transpose_vn(const __half* __restrict__ v, __half* __restrict__ vt)
{
    __shared__ __half t[32][34];
    int s0 = blockIdx.x * 32, d0 = blockIdx.y * 32, b = blockIdx.z;
    #pragma unroll
    for (int i = 0; i < 32; i += 8)
        t[threadIdx.y + i][threadIdx.x] =
            v[((size_t)b*SEQ + s0 + threadIdx.y + i) * D_MODEL + d0 + threadIdx.x];
    __syncthreads();
    #pragma unroll
    for (int i = 0; i < 32; i += 8) {
        int d  = d0 + threadIdx.y + i;
        int h  = d >> 7, hd = d & 127;
        vt[((size_t)((b*NHEAD + h)*HDIM + hd)) * KVTOT + PAST + s0 + threadIdx.x] =
            t[threadIdx.x][threadIdx.y + i];
    }
}

// ---------------------------------------------------------------------------
// fp16 tensor-core flash attention, split-KV (each CTA does half the KV range).
// Block: 64 q rows x (b,h) x kv-half; 4 warps x 16 rows. KV tiles of 64.
// Emits unnormalized O + (m,l) partials; combine kernel merges the two halves.
// ---------------------------------------------------------------------------
#define QT 64
#define KT 64
#define NTH (KVTOT/KT/2)       // 32 tiles per half
#define SQH 136
#define SVH 72
#define OFF_Q      0
#define OFF_K(st)  (8704 + (st)*8704)
#define OFF_VT(st) (26112 + (st)*9216)
#define ATTN_SMEM_H ((26112 + 2*9216)*2)   // 88.5 KB

__global__ __launch_bounds__(128, 2)
void attn_h(const __half* __restrict__ ck)
{
    extern __shared__ __half sm[];
    const uint32_t sbase = smem_u32(sm);
    const int tid  = threadIdx.x;
    const int wid  = tid >> 5;
    const int lane = tid & 31;
    const int r    = lane >> 2;
    const int cc   = lane & 3;
    const int qt   = blockIdx.x >> 1;
    const int kvh  = blockIdx.x & 1;      // which KV half
    const int h  = blockIdx.y;
    const int b  = blockIdx.z;
    const int q0 = qt * QT;
    const int t0 = kvh * NTH;

    const __half* vt_head = g_vt + ((size_t)((b*NHEAD + h)*HDIM)) * KVTOT;

    // Q load (group 0)
    {
        const __half* qg = g_q + ((size_t)(b*SEQ + q0))*D_MODEL + h*HDIM;
        #pragma unroll
        for (int i = 0; i < 8; i++) {
            int s = tid + i*128;
            int row = s >> 4, seg = s & 15;
            cp_async16(sbase + (uint32_t)(OFF_Q + row*SQH + seg*8)*2,
                       qg + (size_t)row*D_MODEL + seg*8);
        }
        cp_commit();
    }

    auto load_tile = [&](int t, int st) {
        int kv0 = t * KT;
        const __half* kb;
        if (kv0 < PAST) kb = ck  + ((size_t)(b*PAST + kv0))*D_MODEL + h*HDIM;
        else            kb = g_k + ((size_t)(b*SEQ + (kv0-PAST)))*D_MODEL + h*HDIM;
        #pragma unroll
        for (int i = 0; i < 8; i++) {
            int s = tid + i*128;
            int row = s >> 4, seg = s & 15;
            cp_async16(sbase + (uint32_t)(OFF_K(st) + row*SQH + seg*8)*2,
                       kb + (size_t)row*D_MODEL + seg*8);
        }
        #pragma unroll
        for (int i = 0; i < 8; i++) {
            int s = tid + i*128;
            int row = s >> 3, seg = s & 7;
            cp_async16(sbase + (uint32_t)(OFF_VT(st) + row*SVH + seg*8)*2,
                       vt_head + (size_t)row*KVTOT + kv0 + seg*8);
        }
        cp_commit();
    };

    load_tile(t0, 0);
    load_tile(t0 + 1, 1);
    cp_wait<1>();
    __syncthreads();

    float o[16][4];
    #pragma unroll
    for (int nj = 0; nj < 16; nj++)
        #pragma unroll
        for (int j = 0; j < 4; j++) o[nj][j] = 0.f;
    float m0 = -1e30f, m1 = -1e30f, l0 = 0.f, l1 = 0.f;

    const float sc = 0.08838834764831845f;   // 1/sqrt(128)

    for (int lt = 0; lt < NTH; lt++) {
        const uint32_t* K32  = (const uint32_t*)(sm + OFF_K(lt & 1));
        const uint32_t* Vt32 = (const uint32_t*)(sm + OFF_VT(lt & 1));
        const uint32_t* pQ   = (const uint32_t*)(sm + OFF_Q) + (wid*16 + r)*(SQH/2) + cc;
        const uint32_t* pK   = K32 + r*(SQH/2) + cc;

        // ---- S = Q @ K^T (m16 n64 k128)
        float s[8][4];
        #pragma unroll
        for (int ni = 0; ni < 8; ni++)
            #pragma unroll
            for (int j = 0; j < 4; j++) s[ni][j] = 0.f;

        #pragma unroll
        for (int ks = 0; ks < 8; ks++) {
            uint32_t a0 = pQ[ks*8];
            uint32_t a1 = pQ[8*(SQH/2) + ks*8];
            uint32_t a2 = pQ[ks*8 + 4];
            uint32_t a3 = pQ[8*(SQH/2) + ks*8 + 4];
            #pragma unroll
            for (int ni = 0; ni < 8; ni++) {
                uint32_t b0 = pK[ni*8*(SQH/2) + ks*8];
                uint32_t b1 = pK[ni*8*(SQH/2) + ks*8 + 4];
                mma_h(s[ni][0], s[ni][1], s[ni][2], s[ni][3],
                      a0, a1, a2, a3, b0, b1);
            }
        }

        // ---- online softmax (rows r and r+8)
        float mx0 = -1e30f, mx1 = -1e30f;
        #pragma unroll
        for (int ni = 0; ni < 8; ni++) {
            s[ni][0] *= sc; s[ni][1] *= sc; s[ni][2] *= sc; s[ni][3] *= sc;
            mx0 = fmaxf(mx0, fmaxf(s[ni][0], s[ni][1]));
            mx1 = fmaxf(mx1, fmaxf(s[ni][2], s[ni][3]));
        }
        mx0 = fmaxf(mx0, __shfl_xor_sync(0xffffffffu, mx0, 1));
        mx0 = fmaxf(mx0, __shfl_xor_sync(0xffffffffu, mx0, 2));
        mx1 = fmaxf(mx1, __shfl_xor_sync(0xffffffffu, mx1, 1));
        mx1 = fmaxf(mx1, __shfl_xor_sync(0xffffffffu, mx1, 2));

        float nm0 = fmaxf(m0, mx0), nm1 = fmaxf(m1, mx1);
        float al0 = __expf(m0 - nm0), al1 = __expf(m1 - nm1);
        float sum0 = 0.f, sum1 = 0.f;
        #pragma unroll
        for (int ni = 0; ni < 8; ni++) {
            s[ni][0] = __expf(s[ni][0] - nm0);
            s[ni][1] = __expf(s[ni][1] - nm0);
            s[ni][2] = __expf(s[ni][2] - nm1);
            s[ni][3] = __expf(s[ni][3] - nm1);
            sum0 += s[ni][0] + s[ni][1];
            sum1 += s[ni][2] + s[ni][3];
        }
        sum0 += __shfl_xor_sync(0xffffffffu, sum0, 1);
        sum0 += __shfl_xor_sync(0xffffffffu, sum0, 2);
        sum1 += __shfl_xor_sync(0xffffffffu, sum1, 1);
        sum1 += __shfl_xor_sync(0xffffffffu, sum1, 2);
        l0 = l0*al0 + sum0;  m0 = nm0;
        l1 = l1*al1 + sum1;  m1 = nm1;

        #pragma unroll
        for (int nj = 0; nj < 16; nj++) {
            o[nj][0] *= al0; o[nj][1] *= al0;
            o[nj][2] *= al1; o[nj][3] *= al1;
        }

        // ---- P: C-fragment -> A-fragment register repack (no smem round-trip)
        // A frag for k-block ks covers C tiles ni=2ks, 2ks+1.
        uint32_t pa[4][4];
        #pragma unroll
        for (int ks = 0; ks < 4; ks++) {
            __half2 h00 = __floats2half2_rn(s[2*ks][0],   s[2*ks][1]);
            __half2 h01 = __floats2half2_rn(s[2*ks][2],   s[2*ks][3]);
            __half2 h10 = __floats2half2_rn(s[2*ks+1][0], s[2*ks+1][1]);
            __half2 h11 = __floats2half2_rn(s[2*ks+1][2], s[2*ks+1][3]);
            pa[ks][0] = *(uint32_t*)&h00;
            pa[ks][1] = *(uint32_t*)&h01;
            pa[ks][2] = *(uint32_t*)&h10;
            pa[ks][3] = *(uint32_t*)&h11;
        }

        // ---- O += P @ V  (m16 n128 k64); B from Vt [hd][kv]
        #pragma unroll
        for (int ks = 0; ks < 4; ks++) {
            #pragma unroll
            for (int nj = 0; nj < 16; nj++) {
                uint32_t b0 = Vt32[(nj*8 + r)*(SVH/2) + ks*8 + cc];
                uint32_t b1 = Vt32[(nj*8 + r)*(SVH/2) + ks*8 + cc + 4];
                mma_h(o[nj][0], o[nj][1], o[nj][2], o[nj][3],
                      pa[ks][0], pa[ks][1], pa[ks][2], pa[ks][3], b0, b1);
            }
        }

        __syncthreads();
        if (lt + 1 < NTH) {
            if (lt + 2 < NTH) { load_tile(t0 + lt + 2, lt & 1); cp_wait<1>(); }
            else              cp_wait<0>();
            __syncthreads();
        }
    }

    // ---- store unnormalized partials
    const int u = ((kvh*BATCH + b)*NHEAD + h)*NQT + qt;
    float* po = g_po + (size_t)u * (QT*HDIM);
    const int row0 = wid*16 + r;
    #pragma unroll
    for (int nj = 0; nj < 16; nj++) {
        *(float2*)(po + row0*HDIM     + nj*8 + 2*cc) = make_float2(o[nj][0], o[nj][1]);
        *(float2*)(po + (row0+8)*HDIM + nj*8 + 2*cc) = make_float2(o[nj][2], o[nj][3]);
    }
    if (cc == 0) {
        g_pm[u*QT + row0]     = m0;  g_pl[u*QT + row0]     = l0;
        g_pm[u*QT + row0 + 8] = m1;  g_pl[u*QT + row0 + 8] = l1;
    }
}

// ---------------------------------------------------------------------------
// Combine the two KV halves -> fp16 g_att
// ---------------------------------------------------------------------------
__global__ void attn_combine(void)
{
    // 65536 rows total (b,h,qt,qrow), 128 cols each. 16 rows/block, 8 cols/thread.
    int rlin = blockIdx.x * 16 + (threadIdx.x >> 4);
    int cs   = (threadIdx.x & 15) * 8;
    int qrow = rlin & 63;
    int qt   = (rlin >> 6) & (NQT-1);
    int h    = (rlin >> 11) & (NHEAD-1);
    int b    = (rlin >> 15) & 1;

    int u0 = ((0*BATCH + b)*NHEAD + h)*NQT + qt;
    int u1 = ((1*BATCH + b)*NHEAD + h)*NQT + qt;

    float m0 = g_pm[u0*QT + qrow], l0 = g_pl[u0*QT + qrow];
    float m1 = g_pm[u1*QT + qrow], l1 = g_pl[u1*QT + qrow];
    float M  = fmaxf(m0, m1);
    float w0 = __expf(m0 - M), w1 = __expf(m1 - M);
    float inv = 1.f / (w0*l0 + w1*l1);
    float f0 = w0 * inv, f1 = w1 * inv;

    const float* p0 = g_po + (size_t)u0*(QT*HDIM) + qrow*HDIM + cs;
    const float* p1 = g_po + (size_t)u1*(QT*HDIM) + qrow*HDIM + cs;
    float4 a0 = *(const float4*)(p0);
    float4 a1 = *(const float4*)(p0 + 4);
    float4 c0 = *(const float4*)(p1);
    float4 c1 = *(const float4*)(p1 + 4);

    __half2 hh[4];
    hh[0] = __floats2half2_rn(f0*a0.x + f1*c0.x, f0*a0.y + f1*c0.y);
    hh[1] = __floats2half2_rn(f0*a0.z + f1*c0.z, f0*a0.w + f1*c0.w);
    hh[2] = __floats2half2_rn(f0*a1.x + f1*c1.x, f0*a1.y + f1*c1.y);
    hh[3] = __floats2half2_rn(f0*a1.z + f1*c1.z, f0*a1.w + f1*c1.w);

    __half* dst = g_att + ((size_t)(b*SEQ + qt*QT + qrow))*D_MODEL + h*HDIM + cs;
    *(uint4*)dst = *(const uint4*)hh;
}

// ---------------------------------------------------------------------------
// Launch
// ---------------------------------------------------------------------------
extern "C" void kernel_launch(void* const* d_in, const int* in_sizes, int n_in,
                              void* d_out, int out_size)
{
    (void)in_sizes; (void)n_in; (void)out_size;
    const float* x  = (const float*)d_in[0];
    const float* ck = (const float*)d_in[1];
    const float* cv = (const float*)d_in[2];
    const float* wq = (const float*)d_in[3];
    const float* bq = (const float*)d_in[4];
    const float* wk = (const float*)d_in[5];
    const float* bk = (const float*)d_in[6];
    const float* wv = (const float*)d_in[7];
    const float* bv = (const float*)d_in[8];
    const float* wo = (const float*)d_in[9];
    const float* bo = (const float*)d_in[10];
    float* out = (float*)d_out;

    __half *pxh, *pq, *pk, *pv, *pa, *pckh, *pvt, *pw;
    cudaGetSymbolAddress((void**)&pxh,  g_xh);
    cudaGetSymbolAddress((void**)&pq,   g_q);
    cudaGetSymbolAddress((void**)&pk,   g_k);
    cudaGetSymbolAddress((void**)&pv,   g_v);
    cudaGetSymbolAddress((void**)&pa,   g_att);
    cudaGetSymbolAddress((void**)&pckh, g_ck);
    cudaGetSymbolAddress((void**)&pvt,  g_vt);
    cudaGetSymbolAddress((void**)&pw,   g_wt);

    __half* wt_q = pw + 0*(size_t)D_MODEL*D_MODEL;
    __half* wt_k = pw + 1*(size_t)D_MODEL*D_MODEL;
    __half* wt_v = pw + 2*(size_t)D_MODEL*D_MODEL;
    __half* wt_o = pw + 3*(size_t)D_MODEL*D_MODEL;

    cudaFuncSetAttribute(gemm_h, cudaFuncAttributeMaxDynamicSharedMemorySize, GEMM_DSMEM);
    cudaFuncSetAttribute(attn_h, cudaFuncAttributeMaxDynamicSharedMemorySize, ATTN_SMEM_H);

    // Prep
    int nx = MROWS*D_MODEL;
    int nc = BATCH*PAST*D_MODEL;
    cvt_h<<<(nx/8 + 255)/256, 256>>>(x,  pxh,  nx);
    cvt_h<<<(nc/8 + 255)/256, 256>>>(ck, pckh, nc);
    dim3 tb(32, 8);
    transpose_w4<<<dim3(D_MODEL/32, D_MODEL/32, 4), tb>>>(wq, wk, wv, wo, pw);
    transpose_vc<<<dim3(PAST/32, D_MODEL/32, BATCH), tb>>>(cv, pvt);

    // Projections
    dim3 gg(D_MODEL/GBN, MROWS/GBM);
    gemm_h<<<gg, 256, GEMM_DSMEM>>>(pxh, wt_q, bq, pq, 1);
    gemm_h<<<gg, 256, GEMM_DSMEM>>>(pxh, wt_k, bk, pk, 1);
    gemm_h<<<gg, 256, GEMM_DSMEM>>>(pxh, wt_v, bv, pv, 1);

    // v_new -> transposed layout
    transpose_vn<<<dim3(SEQ/32, D_MODEL/32, BATCH), tb>>>(pv, pvt);

    // Attention: split-KV (2048 fine-grained units), then combine
    dim3 ag(NQT*2, NHEAD, BATCH);
    attn_h<<<ag, 128, ATTN_SMEM_H>>>(pckh);
    attn_combine<<<(BATCH*NHEAD*NQT*QT)/16, 256>>>();

    // Output projection (fp32 out)
    gemm_h<<<gg, 256, GEMM_DSMEM>>>(pa, wt_o, bo, out, 0);
}

// round 7
// speedup vs baseline: 9.5735x; 1.0581x over previous
#include <cuda_runtime.h>
#include <cuda_fp16.h>
#include <cstdint>
#include <cstddef>

// Problem constants
#define D_MODEL 2048
#define SEQ     2048
#define PAST    2048
#define NHEAD   16
#define HDIM    128
#define BATCH   2
#define MROWS   (BATCH*SEQ)     // 4096
#define KVTOT   (PAST+SEQ)      // 4096
#define NQT     (SEQ/64)        // 32 q-tiles per (b,h)

// Scratch (device globals — allocation-free per harness rules)
__device__ __half g_xh [MROWS*D_MODEL];               // fp16 x
__device__ __half g_q  [MROWS*D_MODEL];
__device__ __half g_k  [MROWS*D_MODEL];
__device__ __half g_v  [MROWS*D_MODEL];
__device__ __half g_att[MROWS*D_MODEL];
__device__ __half g_ck [BATCH*PAST*D_MODEL];          // fp16 cache_k (natural)
__device__ __half g_cv [BATCH*PAST*D_MODEL];          // fp16 cache_v (natural)
__device__ __half g_wt [4*(size_t)D_MODEL*D_MODEL];   // transposed fp16 weights (q,k,v,o)
// split-KV partials: [half][b][h][qt][64 rows][128 cols]
__device__ __half g_po [2*BATCH*NHEAD*NQT*64*128];    // 67 MB
__device__ float  g_pm [2*BATCH*NHEAD*NQT*64];
__device__ float  g_pl [2*BATCH*NHEAD*NQT*64];

// ---------------------------------------------------------------------------
// helpers
// ---------------------------------------------------------------------------
__device__ __forceinline__ uint32_t smem_u32(const void* p) {
    uint32_t a;
    asm("{ .reg .u64 t; cvta.to.shared.u64 t, %1; cvt.u32.u64 %0, t; }" : "=r"(a) : "l"(p));
    return a;
}
__device__ __forceinline__ void cp_async16(uint32_t sdst, const void* gsrc) {
    asm volatile("cp.async.cg.shared.global [%0], [%1], 16;" :: "r"(sdst), "l"(gsrc));
}
__device__ __forceinline__ void cp_commit() {
    asm volatile("cp.async.commit_group;");
}
template<int N>
__device__ __forceinline__ void cp_wait() {
    asm volatile("cp.async.wait_group %0;" :: "n"(N));
}
__device__ __forceinline__ void mma_h(float& c0, float& c1, float& c2, float& c3,
                                      uint32_t a0, uint32_t a1, uint32_t a2, uint32_t a3,
                                      uint32_t b0, uint32_t b1) {
    asm volatile("mma.sync.aligned.m16n8k16.row.col.f32.f16.f16.f32 "
                 "{%0,%1,%2,%3}, {%4,%5,%6,%7}, {%8,%9}, {%0,%1,%2,%3};"
                 : "+f"(c0), "+f"(c1), "+f"(c2), "+f"(c3)
                 : "r"(a0), "r"(a1), "r"(a2), "r"(a3), "r"(b0), "r"(b1));
}
__device__ __forceinline__ void ldsm_x4(uint32_t& r0, uint32_t& r1, uint32_t& r2, uint32_t& r3,
                                        uint32_t addr) {
    asm volatile("ldmatrix.sync.aligned.m8n8.x4.shared.b16 {%0,%1,%2,%3}, [%4];"
                 : "=r"(r0), "=r"(r1), "=r"(r2), "=r"(r3) : "r"(addr));
}
__device__ __forceinline__ void ldsm_x4_t(uint32_t& r0, uint32_t& r1, uint32_t& r2, uint32_t& r3,
                                          uint32_t addr) {
    asm volatile("ldmatrix.sync.aligned.m8n8.x4.trans.shared.b16 {%0,%1,%2,%3}, [%4];"
                 : "=r"(r0), "=r"(r1), "=r"(r2), "=r"(r3) : "r"(addr));
}

// ---------------------------------------------------------------------------
// fp16 GEMM core (CTA 128x256, BK=64, 8 warps, warp tile 64x64, 3-stage)
// ---------------------------------------------------------------------------
#define GBM 128
#define GBN 256
#define GBK 64
#define SWH 72
#define AS_H (GBM*SWH)
#define BS_H (GBN*SWH)
#define STG_H (AS_H+BS_H)
#define GSTG 3
#define GEMM_DSMEM (GSTG*STG_H*2)
#define NCHUNK (D_MODEL/GBK)

struct GemmCore {
    __device__ static void run(const __half* A, const __half* Bt,
                               const float* bias, void* Cout, int half_out,
                               int m0, int n0glob, int ncol0, __half* sh)
    {
        const uint32_t sbase = smem_u32(sh);
        const int tid  = threadIdx.x;
        const int wid  = tid >> 5;
        const int lane = tid & 31;
        const int r    = lane >> 2;
        const int cc   = lane & 3;
        const int wm = (wid >> 2) * 64;
        const int wn = (wid & 3) * 64;

        const int row8 = tid >> 3;
        const int seg  = tid & 7;
        const __half* Ag = A  + (size_t)(m0 + row8) * D_MODEL + seg * 8;
        const __half* Bg = Bt + (size_t)(n0glob + row8) * D_MODEL + seg * 8;

        float c[4][8][4];
        #pragma unroll
        for (int mi = 0; mi < 4; mi++)
            #pragma unroll
            for (int ni = 0; ni < 8; ni++)
                #pragma unroll
                for (int j = 0; j < 4; j++) c[mi][ni][j] = 0.f;

        auto load_chunk = [&](int chunk, int st) {
            uint32_t as = sbase + (st*STG_H) * 2;
            uint32_t bs = as + AS_H * 2;
            const __half* ag = Ag + chunk * GBK;
            const __half* bg = Bg + chunk * GBK;
            #pragma unroll
            for (int i = 0; i < 4; i++) {
                int row = row8 + i * 32;
                cp_async16(as + (uint32_t)(row*SWH + seg*8)*2, ag + (size_t)i*32*D_MODEL);
            }
            #pragma unroll
            for (int i = 0; i < 8; i++) {
                int row = row8 + i * 32;
                cp_async16(bs + (uint32_t)(row*SWH + seg*8)*2, bg + (size_t)i*32*D_MODEL);
            }
            cp_commit();
        };

        load_chunk(0, 0);
        load_chunk(1, 1);
        load_chunk(2, 2);

        for (int ch = 0; ch < NCHUNK; ch++) {
            int rem = NCHUNK - 1 - ch;
            if (rem >= 2)      cp_wait<2>();
            else if (rem == 1) cp_wait<1>();
            else               cp_wait<0>();
            __syncthreads();

            int st = ch % GSTG;
            const uint32_t* As32 = (const uint32_t*)(sh + st * STG_H);
            const uint32_t* Bs32 = As32 + AS_H/2;
            const uint32_t* pA = As32 + (wm + r) * (SWH/2) + cc;
            const uint32_t* pB = Bs32 + (wn + r) * (SWH/2) + cc;

            #pragma unroll
            for (int ks = 0; ks < 4; ks++) {
                uint32_t a[4][4];
                #pragma unroll
                for (int mi = 0; mi < 4; mi++) {
                    const uint32_t* p = pA + mi*16*(SWH/2) + ks*8;
                    a[mi][0] = p[0];
                    a[mi][1] = p[8*(SWH/2)];
                    a[mi][2] = p[4];
                    a[mi][3] = p[8*(SWH/2) + 4];
                }
                uint32_t b[8][2];
                #pragma unroll
                for (int ni = 0; ni < 8; ni++) {
                    const uint32_t* p = pB + ni*8*(SWH/2) + ks*8;
                    b[ni][0] = p[0];
                    b[ni][1] = p[4];
                }
                #pragma unroll
                for (int mi = 0; mi < 4; mi++)
                    #pragma unroll
                    for (int ni = 0; ni < 8; ni++)
                        mma_h(c[mi][ni][0], c[mi][ni][1], c[mi][ni][2], c[mi][ni][3],
                              a[mi][0], a[mi][1], a[mi][2], a[mi][3],
                              b[ni][0], b[ni][1]);
            }
            __syncthreads();
            if (ch + GSTG < NCHUNK) load_chunk(ch + GSTG, st);
        }

        #pragma unroll
        for (int mi = 0; mi < 4; mi++) {
            int row = m0 + wm + mi*16 + r;
            #pragma unroll
            for (int ni = 0; ni < 8; ni++) {
                int col = ncol0 + wn + ni*8 + cc*2;
                float2 bv = *(const float2*)(bias + col);
                float o00 = c[mi][ni][0] + bv.x, o01 = c[mi][ni][1] + bv.y;
                float o10 = c[mi][ni][2] + bv.x, o11 = c[mi][ni][3] + bv.y;
                if (half_out) {
                    __half* Ch = (__half*)Cout;
                    *(__half2*)(Ch + (size_t)row*D_MODEL + col)     = __floats2half2_rn(o00, o01);
                    *(__half2*)(Ch + (size_t)(row+8)*D_MODEL + col) = __floats2half2_rn(o10, o11);
                } else {
                    float* Cf = (float*)Cout;
                    *(float2*)(Cf + (size_t)row*D_MODEL + col)     = make_float2(o00, o01);
                    *(float2*)(Cf + (size_t)(row+8)*D_MODEL + col) = make_float2(o10, o11);
                }
            }
        }
    }
};

// fused QKV: Bt rows 0..6143 = wq^T | wk^T | wv^T
__global__ __launch_bounds__(256, 1)
void gemm_qkv(const __half* __restrict__ A, const __half* __restrict__ BtAll,
              const float* __restrict__ bq, const float* __restrict__ bk,
              const float* __restrict__ bv,
              __half* __restrict__ Cq, __half* __restrict__ Ck, __half* __restrict__ Cv)
{
    extern __shared__ __half sh[];
    int n0g = blockIdx.x * GBN;
    int mat = n0g >> 11;
    const float* bias = (mat == 0) ? bq : (mat == 1) ? bk : bv;
    __half* C = (mat == 0) ? Cq : (mat == 1) ? Ck : Cv;
    GemmCore::run(A, BtAll, bias, C, 1, blockIdx.y * GBM, n0g, n0g & 2047, sh);
}

__global__ __launch_bounds__(256, 1)
void gemm_o(const __half* __restrict__ A, const __half* __restrict__ Bt,
            const float* __restrict__ bias, float* __restrict__ C)
{
    extern __shared__ __half sh[];
    int n0 = blockIdx.x * GBN;
    GemmCore::run(A, Bt, bias, C, 0, blockIdx.y * GBM, n0, n0, sh);
}

// ---------------------------------------------------------------------------
// Prep kernels
// ---------------------------------------------------------------------------
__global__ void cvt3_h(const float* __restrict__ x, const float* __restrict__ ck,
                       const float* __restrict__ cv,
                       __half* __restrict__ dx, __half* __restrict__ dck,
                       __half* __restrict__ dcv)
{
    const float* src = (blockIdx.y == 0) ? x : (blockIdx.y == 1) ? ck : cv;
    __half* dst = (blockIdx.y == 0) ? dx : (blockIdx.y == 1) ? dck : dcv;
    int i = (blockIdx.x * blockDim.x + threadIdx.x) * 8;
    float4 f0 = *(const float4*)(src + i);
    float4 f1 = *(const float4*)(src + i + 4);
    __half2 h[4];
    h[0] = __floats2half2_rn(f0.x, f0.y);
    h[1] = __floats2half2_rn(f0.z, f0.w);
    h[2] = __floats2half2_rn(f1.x, f1.y);
    h[3] = __floats2half2_rn(f1.z, f1.w);
    *(uint4*)(dst + i) = *(const uint4*)h;
}

__global__ void transpose_w4(const float* __restrict__ w0, const float* __restrict__ w1,
                             const float* __restrict__ w2, const float* __restrict__ w3,
                             __half* __restrict__ dstBase)
{
    __shared__ float t[32][33];
    const float* src = (blockIdx.z == 0) ? w0 : (blockIdx.z == 1) ? w1 :
                       (blockIdx.z == 2) ? w2 : w3;
    __half* dst = dstBase + (size_t)blockIdx.z * D_MODEL * D_MODEL;
    int bx = blockIdx.x * 32, by = blockIdx.y * 32;
    int x = bx + threadIdx.x;
    #pragma unroll
    for (int i = 0; i < 32; i += 8)
        t[threadIdx.y + i][threadIdx.x] = src[(size_t)(by + threadIdx.y + i) * D_MODEL + x];
    __syncthreads();
    x = by + threadIdx.x;
    #pragma unroll
    for (int i = 0; i < 32; i += 8)
        dst[(size_t)(bx + threadIdx.y + i) * D_MODEL + x] = __float2half(t[threadIdx.x][threadIdx.y + i]);
}

// ---------------------------------------------------------------------------
// fp16 flash attention, split-KV, ldmatrix fragments, K and V in natural layout.
// Block: 64 q rows x (b,h) x kv-half; 4 warps x 16 rows; KV tiles of 64, 2-stage.
// ---------------------------------------------------------------------------
#define QT 64
#define KT 64
#define NTH (KVTOT/KT/2)       // 32 tiles per half
#define SQH 136                // row stride (halfs) for Q/K/V tiles
#define OFF_Q      0
#define OFF_K(st)  (8704 + (st)*8704)
#define OFF_V(st)  (26112 + (st)*8704)
#define ATTN_SMEM_H ((26112 + 2*8704)*2)   // 87040 bytes

__global__ __launch_bounds__(128, 2)
void attn_h(void)
{
    extern __shared__ __half sm[];
    const uint32_t sbase = smem_u32(sm);
    const int tid  = threadIdx.x;
    const int wid  = tid >> 5;
    const int lane = tid & 31;
    const int r    = lane >> 2;
    const int cc   = lane & 3;
    const int qt   = blockIdx.x >> 1;
    const int kvh  = blockIdx.x & 1;
    const int h  = blockIdx.y;
    const int b  = blockIdx.z;
    const int q0 = qt * QT;
    const int t0 = kvh * NTH;

    // Q load (group 0)
    {
        const __half* qg = g_q + ((size_t)(b*SEQ + q0))*D_MODEL + h*HDIM;
        #pragma unroll
        for (int i = 0; i < 8; i++) {
            int s = tid + i*128;
            int row = s >> 4, seg = s & 15;
            cp_async16(sbase + (uint32_t)(OFF_Q + row*SQH + seg*8)*2,
                       qg + (size_t)row*D_MODEL + seg*8);
        }
        cp_commit();
    }

    auto load_tile = [&](int t, int st) {
        int kv0 = t * KT;
        const __half *kb, *vb;
        if (kv0 < PAST) {
            size_t off = ((size_t)(b*PAST + kv0))*D_MODEL + h*HDIM;
            kb = g_ck + off; vb = g_cv + off;
        } else {
            size_t off = ((size_t)(b*SEQ + (kv0-PAST)))*D_MODEL + h*HDIM;
            kb = g_k + off; vb = g_v + off;
        }
        #pragma unroll
        for (int i = 0; i < 8; i++) {
            int s = tid + i*128;
            int row = s >> 4, seg = s & 15;
            cp_async16(sbase + (uint32_t)(OFF_K(st) + row*SQH + seg*8)*2,
                       kb + (size_t)row*D_MODEL + seg*8);
            cp_async16(sbase + (uint32_t)(OFF_V(st) + row*SQH + seg*8)*2,
                       vb + (size_t)row*D_MODEL + seg*8);
        }
        cp_commit();
    };

    load_tile(t0, 0);
    load_tile(t0 + 1, 1);
    cp_wait<1>();
    __syncthreads();

    // ---- hoist Q A-fragments for all 8 k16-blocks (ldmatrix x4 non-trans)
    // groups: g0 rows+0 col+0 | g1 rows+8 col+0 | g2 rows+0 col+8 | g3 rows+8 col+8
    uint32_t qa[8][4];
    {
        int g  = lane >> 3, kr = lane & 7;
        int qrow = wid*16 + (g & 1)*8 + kr;
        int cbase = (g >> 1)*8;
        #pragma unroll
        for (int kb = 0; kb < 8; kb++) {
            uint32_t addr = sbase + (uint32_t)(OFF_Q + qrow*SQH + kb*16 + cbase)*2;
            ldsm_x4(qa[kb][0], qa[kb][1], qa[kb][2], qa[kb][3], addr);
        }
    }

    float o[16][4];
    #pragma unroll
    for (int nj = 0; nj < 16; nj++)
        #pragma unroll
        for (int j = 0; j < 4; j++) o[nj][j] = 0.f;
    float m0 = -1e30f, m1 = -1e30f, l0 = 0.f, l1 = 0.f;

    const float sc = 0.08838834764831845f;   // 1/sqrt(128)

    // ldmatrix lane-address precomputes
    // K (non-trans B): g0: n+0 k+0 | g1: n+0 k+8 | g2: n+8 k+0 | g3: n+8 k+8
    const int kg = lane >> 3, kkr = lane & 7;
    const int k_row_off = (kg >> 1)*8 + kkr;
    const int k_col_off = (kg & 1)*8;
    // V (trans B): lanes 0-15: rows k 0-15 col n+0 ; lanes 16-31: rows k 0-15 col n+8
    const int v_row_off = lane & 15;
    const int v_col_off = (lane >> 4)*8;

    for (int lt = 0; lt < NTH; lt++) {
        const uint32_t kbase = sbase + (uint32_t)OFF_K(lt & 1)*2;
        const uint32_t vbase = sbase + (uint32_t)OFF_V(lt & 1)*2;

        // ---- S = Q @ K^T (m16 n64 k128): 4 n-pairs x 8 k16-blocks
        float s[8][4];
        #pragma unroll
        for (int ni = 0; ni < 8; ni++)
            #pragma unroll
            for (int j = 0; j < 4; j++) s[ni][j] = 0.f;

        #pragma unroll
        for (int np = 0; np < 4; np++) {
            #pragma unroll
            for (int kb = 0; kb < 8; kb++) {
                uint32_t b0, b1, b2, b3;
                uint32_t addr = kbase + (uint32_t)((np*16 + k_row_off)*SQH + kb*16 + k_col_off)*2;
                ldsm_x4(b0, b1, b2, b3, addr);
                mma_h(s[2*np][0], s[2*np][1], s[2*np][2], s[2*np][3],
                      qa[kb][0], qa[kb][1], qa[kb][2], qa[kb][3], b0, b1);
                mma_h(s[2*np+1][0], s[2*np+1][1], s[2*np+1][2], s[2*np+1][3],
                      qa[kb][0], qa[kb][1], qa[kb][2], qa[kb][3], b2, b3);
            }
        }

        // ---- online softmax (rows r and r+8)
        float mx0 = -1e30f, mx1 = -1e30f;
        #pragma unroll
        for (int ni = 0; ni < 8; ni++) {
            s[ni][0] *= sc; s[ni][1] *= sc; s[ni][2] *= sc; s[ni][3] *= sc;
            mx0 = fmaxf(mx0, fmaxf(s[ni][0], s[ni][1]));
            mx1 = fmaxf(mx1, fmaxf(s[ni][2], s[ni][3]));
        }
        mx0 = fmaxf(mx0, __shfl_xor_sync(0xffffffffu, mx0, 1));
        mx0 = fmaxf(mx0, __shfl_xor_sync(0xffffffffu, mx0, 2));
        mx1 = fmaxf(mx1, __shfl_xor_sync(0xffffffffu, mx1, 1));
        mx1 = fmaxf(mx1, __shfl_xor_sync(0xffffffffu, mx1, 2));

        float nm0 = fmaxf(m0, mx0), nm1 = fmaxf(m1, mx1);
        float al0 = __expf(m0 - nm0), al1 = __expf(m1 - nm1);
        float sum0 = 0.f, sum1 = 0.f;
        #pragma unroll
        for (int ni = 0; ni < 8; ni++) {
            s[ni][0] = __expf(s[ni][0] - nm0);
            s[ni][1] = __expf(s[ni][1] - nm0);
            s[ni][2] = __expf(s[ni][2] - nm1);
            s[ni][3] = __expf(s[ni][3] - nm1);
            sum0 += s[ni][0] + s[ni][1];
            sum1 += s[ni][2] + s[ni][3];
        }
        sum0 += __shfl_xor_sync(0xffffffffu, sum0, 1);
        sum0 += __shfl_xor_sync(0xffffffffu, sum0, 2);
        sum1 += __shfl_xor_sync(0xffffffffu, sum1, 1);
        sum1 += __shfl_xor_sync(0xffffffffu, sum1, 2);
        l0 = l0*al0 + sum0;  m0 = nm0;
        l1 = l1*al1 + sum1;  m1 = nm1;

        #pragma unroll
        for (int nj = 0; nj < 16; nj++) {
            o[nj][0] *= al0; o[nj][1] *= al0;
            o[nj][2] *= al1; o[nj][3] *= al1;
        }

        // ---- P: C-fragment -> A-fragment register repack
        uint32_t pa[4][4];
        #pragma unroll
        for (int ks = 0; ks < 4; ks++) {
            __half2 h00 = __floats2half2_rn(s[2*ks][0],   s[2*ks][1]);
            __half2 h01 = __floats2half2_rn(s[2*ks][2],   s[2*ks][3]);
            __half2 h10 = __floats2half2_rn(s[2*ks+1][0], s[2*ks+1][1]);
            __half2 h11 = __floats2half2_rn(s[2*ks+1][2], s[2*ks+1][3]);
            pa[ks][0] = *(uint32_t*)&h00;
            pa[ks][1] = *(uint32_t*)&h01;
            pa[ks][2] = *(uint32_t*)&h10;
            pa[ks][3] = *(uint32_t*)&h11;
        }

        // ---- O += P @ V  (m16 n128 k64); B frags via ldmatrix.trans on natural V
        #pragma unroll
        for (int np = 0; np < 8; np++) {
            #pragma unroll
            for (int ks = 0; ks < 4; ks++) {
                uint32_t v0, v1, v2, v3;
                uint32_t addr = vbase + (uint32_t)((ks*16 + v_row_off)*SQH + np*16 + v_col_off)*2;
                ldsm_x4_t(v0, v1, v2, v3, addr);
                mma_h(o[2*np][0], o[2*np][1], o[2*np][2], o[2*np][3],
                      pa[ks][0], pa[ks][1], pa[ks][2], pa[ks][3], v0, v1);
                mma_h(o[2*np+1][0], o[2*np+1][1], o[2*np+1][2], o[2*np+1][3],
                      pa[ks][0], pa[ks][1], pa[ks][2], pa[ks][3], v2, v3);
            }
        }

        __syncthreads();
        if (lt + 1 < NTH) {
            if (lt + 2 < NTH) { load_tile(t0 + lt + 2, lt & 1); cp_wait<1>(); }
            else              cp_wait<0>();
            __syncthreads();
        }
    }

    // ---- store unnormalized fp16 partials + (m,l)
    const int u = ((kvh*BATCH + b)*NHEAD + h)*NQT + qt;
    __half* po = g_po + (size_t)u * (QT*HDIM);
    const int row0 = wid*16 + r;
    #pragma unroll
    for (int nj = 0; nj < 16; nj++) {
        __half2 h0 = __floats2half2_rn(o[nj][0], o[nj][1]);
        __half2 h1 = __floats2half2_rn(o[nj][2], o[nj][3]);
        *(__half2*)(po + row0*HDIM     + nj*8 + 2*cc) = h0;
        *(__half2*)(po + (row0+8)*HDIM + nj*8 + 2*cc) = h1;
    }
    if (cc == 0) {
        g_pm[u*QT + row0]     = m0;  g_pl[u*QT + row0]     = l0;
        g_pm[u*QT + row0 + 8] = m1;  g_pl[u*QT + row0 + 8] = l1;
    }
}

// ---------------------------------------------------------------------------
// Combine the two KV halves -> fp16 g_att
// ---------------------------------------------------------------------------
__global__ void attn_combine(void)
{
    int rlin = blockIdx.x * 16 + (threadIdx.x >> 4);
    int cs   = (threadIdx.x & 15) * 8;
    int qrow = rlin & 63;
    int qt   = (rlin >> 6) & (NQT-1);
    int h    = (rlin >> 11) & (NHEAD-1);
    int b    = (rlin >> 15) & 1;

    int u0 = ((0*BATCH + b)*NHEAD + h)*NQT + qt;
    int u1 = ((1*BATCH + b)*NHEAD + h)*NQT + qt;

    float m0 = g_pm[u0*QT + qrow], l0 = g_pl[u0*QT + qrow];
    float m1 = g_pm[u1*QT + qrow], l1 = g_pl[u1*QT + qrow];
    float M  = fmaxf(m0, m1);
    float w0 = __expf(m0 - M), w1 = __expf(m1 - M);
    float inv = 1.f / (w0*l0 + w1*l1);
    float f0 = w0 * inv, f1 = w1 * inv;

    const __half* p0 = g_po + (size_t)u0*(QT*HDIM) + qrow*HDIM + cs;
    const __half* p1 = g_po + (size_t)u1*(QT*HDIM) + qrow*HDIM + cs;
    uint4 r0 = *(const uint4*)p0;
    uint4 r1 = *(const uint4*)p1;
    const __half2* a = (const __half2*)&r0;
    const __half2* c = (const __half2*)&r1;

    __half2 hh[4];
    #pragma unroll
    for (int j = 0; j < 4; j++) {
        float2 fa = __half22float2(a[j]);
        float2 fc = __half22float2(c[j]);
        hh[j] = __floats2half2_rn(f0*fa.x + f1*fc.x, f0*fa.y + f1*fc.y);
    }

    __half* dst = g_att + ((size_t)(b*SEQ + qt*QT + qrow))*D_MODEL + h*HDIM + cs;
    *(uint4*)dst = *(const uint4*)hh;
}

// ---------------------------------------------------------------------------
// Launch
// ---------------------------------------------------------------------------
extern "C" void kernel_launch(void* const* d_in, const int* in_sizes, int n_in,
                              void* d_out, int out_size)
{
    (void)in_sizes; (void)n_in; (void)out_size;
    const float* x  = (const float*)d_in[0];
    const float* ck = (const float*)d_in[1];
    const float* cv = (const float*)d_in[2];
    const float* wq = (const float*)d_in[3];
    const float* bq = (const float*)d_in[4];
    const float* wk = (const float*)d_in[5];
    const float* bk = (const float*)d_in[6];
    const float* wv = (const float*)d_in[7];
    const float* bv = (const float*)d_in[8];
    const float* wo = (const float*)d_in[9];
    const float* bo = (const float*)d_in[10];
    float* out = (float*)d_out;

    __half *pxh, *pq, *pk, *pv, *pa, *pckh, *pcvh, *pw;
    cudaGetSymbolAddress((void**)&pxh,  g_xh);
    cudaGetSymbolAddress((void**)&pq,   g_q);
    cudaGetSymbolAddress((void**)&pk,   g_k);
    cudaGetSymbolAddress((void**)&pv,   g_v);
    cudaGetSymbolAddress((void**)&pa,   g_att);
    cudaGetSymbolAddress((void**)&pckh, g_ck);
    cudaGetSymbolAddress((void**)&pcvh, g_cv);
    cudaGetSymbolAddress((void**)&pw,   g_wt);

    __half* wt_o = pw + 3*(size_t)D_MODEL*D_MODEL;

    cudaFuncSetAttribute(gemm_qkv, cudaFuncAttributeMaxDynamicSharedMemorySize, GEMM_DSMEM);
    cudaFuncSetAttribute(gemm_o,   cudaFuncAttributeMaxDynamicSharedMemorySize, GEMM_DSMEM);
    cudaFuncSetAttribute(attn_h,   cudaFuncAttributeMaxDynamicSharedMemorySize, ATTN_SMEM_H);

    // Prep: one fused conversion launch (x, cache_k, cache_v all 8.4M elems)
    cvt3_h<<<dim3(MROWS*D_MODEL/8/256, 3), 256>>>(x, ck, cv, pxh, pckh, pcvh);
    dim3 tb(32, 8);
    transpose_w4<<<dim3(D_MODEL/32, D_MODEL/32, 4), tb>>>(wq, wk, wv, wo, pw);

    // Fused QKV projection
    gemm_qkv<<<dim3(3*D_MODEL/GBN, MROWS/GBM), 256, GEMM_DSMEM>>>(
        pxh, pw, bq, bk, bv, pq, pk, pv);

    // Attention: split-KV + combine
    dim3 ag(NQT*2, NHEAD, BATCH);
    attn_h<<<ag, 128, ATTN_SMEM_H>>>();
    attn_combine<<<(BATCH*NHEAD*NQT*QT)/16, 256>>>();

    // Output projection (fp32 out)
    gemm_o<<<dim3(D_MODEL/GBN, MROWS/GBM), 256, GEMM_DSMEM>>>(pa, wt_o, bo, out);
}